// round 2
// baseline (speedup 1.0000x reference)
#include <cuda_runtime.h>
#include <stdint.h>

// Problem constants
#define MG 8      // number of quantizer groups (m)
#define KC 4096   // codebook entries per group
#define DD 128    // dim
#define NB 8      // batch
#define HH 64
#define WW 64

// Scratch: transformed codebook T[m][k][c] = codebook[m][k] @ wq[m]^T + bq[m]
// 8*4096*128 f32 = 16 MB (fits in L2 for the gather phase)
__device__ float g_T[MG * KC * DD];

// ---------------------------------------------------------------------------
// Phase 1: T[m][k][c] = sum_d codebook[m][k][d] * wq[m][c][d] + bq[m][c]
// grid = (64 k-tiles, 8 m), block = 256 threads.
// Each block computes a 64(k) x 128(c) tile; each thread an 8x4 register tile.
// ---------------------------------------------------------------------------
__global__ void __launch_bounds__(256, 4) phase1_gemm(
    const float* __restrict__ codebook,
    const float* __restrict__ wq,
    const float* __restrict__ bq)
{
    const int m  = blockIdx.y;
    const int k0 = blockIdx.x * 64;
    const int tid = threadIdx.x;
    const int tk = tid >> 5;   // warp id 0..7 -> k sub-group (warp-uniform)
    const int tc = tid & 31;   // lane      -> c group (4 consecutive c)

    __shared__ float sA[64][33];    // [k][d-chunk], +1 pad
    __shared__ float sW[32][132];   // [d-chunk][c], pad 132 (16B-aligned rows)

    const float* A  = codebook + ((size_t)m * KC + k0) * DD;
    const float* Wm = wq + (size_t)m * DD * DD;

    float acc[8][4];
    #pragma unroll
    for (int i = 0; i < 8; i++)
        #pragma unroll
        for (int j = 0; j < 4; j++) acc[i][j] = 0.f;

    for (int d0 = 0; d0 < DD; d0 += 32) {
        // Load A chunk: 64 rows x 32 d (coalesced 128B per row)
        #pragma unroll
        for (int t = 0; t < 8; t++) {
            int idx = tid + t * 256;       // 0..2047
            int r = idx >> 5, dd = idx & 31;
            sA[r][dd] = A[r * DD + d0 + dd];
        }
        // Load W chunk transposed: sW[dd][c], 128 c x 32 d
        #pragma unroll
        for (int t = 0; t < 16; t++) {
            int idx = tid + t * 256;       // 0..4095
            int c = idx >> 5, dd = idx & 31;
            sW[dd][c] = Wm[c * DD + d0 + dd];
        }
        __syncthreads();

        #pragma unroll
        for (int dd = 0; dd < 32; dd++) {
            // vectorized, conflict-free (row is 16B-aligned with pad 132)
            float4 wv = *reinterpret_cast<const float4*>(&sW[dd][tc * 4]);
            #pragma unroll
            for (int i = 0; i < 8; i++) {
                float a = sA[tk * 8 + i][dd];   // warp-uniform broadcast
                acc[i][0] += a * wv.x;
                acc[i][1] += a * wv.y;
                acc[i][2] += a * wv.z;
                acc[i][3] += a * wv.w;
            }
        }
        __syncthreads();
    }

    // Epilogue: add bias, store T tile (STG.128, fully coalesced)
    float4 bias = *reinterpret_cast<const float4*>(&bq[m * DD + tc * 4]);
    float* Tm = g_T + ((size_t)m * KC + k0) * DD;
    #pragma unroll
    for (int i = 0; i < 8; i++) {
        float4 v;
        v.x = acc[i][0] + bias.x;
        v.y = acc[i][1] + bias.y;
        v.z = acc[i][2] + bias.z;
        v.w = acc[i][3] + bias.w;
        *reinterpret_cast<float4*>(&Tm[(tk * 8 + i) * DD + tc * 4]) = v;
    }
}

// ---------------------------------------------------------------------------
// Phase 2: gather + transpose.
// out[n][m*128+c][h][w] = T[m][codes[n][h][w][m]][c]
// grid = (h=64, m=8, n=8) -> 4096 blocks, 256 threads.
// Each block handles one (n,h,m) row of 64 w-tokens:
//   1) gather 64 T-rows (512B each) into smem, coalesced 128B loads from L2
//   2) write transposed: 256B coalesced stores per (c, w-row) to HBM
// smem row pad = 129 words -> bank-conflict-free on both STS and LDS.
// codes are INT32 (jax x64 disabled downcasts jnp.int64 -> int32).
// Index masked with (KC-1): no-op for valid codes, guards OOB if dtype wrong.
// ---------------------------------------------------------------------------
__global__ void __launch_bounds__(256, 4) phase2_gather(
    const int* __restrict__ codes,
    float* __restrict__ out)
{
    const int h = blockIdx.x;
    const int m = blockIdx.y;
    const int n = blockIdx.z;
    const int tid  = threadIdx.x;
    const int lane = tid & 31;
    const int wid  = tid >> 5;   // 0..7

    __shared__ float s[64][129];   // [w][c]
    __shared__ int scode[64];

    // Load 64 codes for this (n, h, :, m)
    if (tid < 64) {
        scode[tid] = codes[(((size_t)n * HH + h) * WW + tid) * MG + m] & (KC - 1);
    }
    __syncthreads();

    // Gather T rows: each warp loads 8 rows, 4 scalar f32 per lane per row
    // (lanes cover 128B contiguous chunks -> coalesced; mostly L2 hits)
    const float* Tm = g_T + (size_t)m * KC * DD;
    #pragma unroll
    for (int t = 0; t < 8; t++) {
        int w = wid + t * 8;
        const float* Trow = Tm + (size_t)scode[w] * DD;
        #pragma unroll
        for (int q = 0; q < 4; q++) {
            s[w][lane + 32 * q] = __ldg(&Trow[lane + 32 * q]);
        }
    }
    __syncthreads();

    // Transposed write-out: thread (c = tid/64 + 4*pass, w = tid%64)
    // 64 consecutive threads write 64 consecutive w -> 256B coalesced stores
    const int w = tid & 63;
    const int cbase = tid >> 6;   // 0..3
    float* outbase = out + ((((size_t)n * (MG * DD) + m * DD) * HH + h) * WW) + w;
    #pragma unroll
    for (int pass = 0; pass < 32; pass++) {
        int c = cbase + pass * 4;
        outbase[(size_t)c * HH * WW] = s[w][c];
    }
}

// ---------------------------------------------------------------------------
// Launch
// Inputs (metadata order): codes[int32], codebook[f32], wq[f32], bq[f32]
// ---------------------------------------------------------------------------
extern "C" void kernel_launch(void* const* d_in, const int* in_sizes, int n_in,
                              void* d_out, int out_size) {
    const int*   codes    = (const int*)d_in[0];
    const float* codebook = (const float*)d_in[1];
    const float* wq       = (const float*)d_in[2];
    const float* bq       = (const float*)d_in[3];
    float* out = (float*)d_out;

    dim3 g1(KC / 64, MG);
    phase1_gemm<<<g1, 256>>>(codebook, wq, bq);

    dim3 g2(HH, MG, NB);
    phase2_gather<<<g2, 256>>>(codes, out);
}

// round 4
// speedup vs baseline: 1.1119x; 1.1119x over previous
#include <cuda_runtime.h>
#include <stdint.h>

// Problem constants
#define MG 8      // number of quantizer groups (m)
#define KC 4096   // codebook entries per group
#define DD 128    // dim
#define NB 8      // batch
#define HH 64
#define WW 64

// Scratch: transformed codebook T[m][k][c] = codebook[m][k] @ wq[m]^T + bq[m]
// 8*4096*128 f32 = 16 MB (resident in L2 for the gather phase)
__device__ float g_T[MG * KC * DD];

// ---- packed fp32x2 helpers (Blackwell: 2x fp32 FMA throughput) ----
__device__ __forceinline__ unsigned long long pack2(float lo, float hi) {
    unsigned long long r;
    asm("mov.b64 %0, {%1, %2};" : "=l"(r) : "f"(lo), "f"(hi));
    return r;
}
__device__ __forceinline__ void unpack2(unsigned long long v, float& lo, float& hi) {
    asm("mov.b64 {%0, %1}, %2;" : "=f"(lo), "=f"(hi) : "l"(v));
}
__device__ __forceinline__ void fma2(unsigned long long& acc,
                                     unsigned long long a,
                                     unsigned long long b) {
    asm("fma.rn.f32x2 %0, %1, %2, %0;" : "+l"(acc) : "l"(a), "l"(b));
}

// ---------------------------------------------------------------------------
// Phase 1: T[m][k][c] = sum_d codebook[m][k][d] * wq[m][c][d] + bq[m][c]
// grid = (64 k-tiles, 8 m), block = 256 threads, tile 64(k) x 128(c).
// Thread tile: 8 k x 4 c, accumulated as 4 k-pairs x 4 c in f32x2 registers.
// A is staged TRANSPOSED in smem (sAT[d][k]) so a k-pair is one LDS.64.
// ---------------------------------------------------------------------------
__global__ void __launch_bounds__(256, 4) phase1_gemm(
    const float* __restrict__ codebook,
    const float* __restrict__ wq,
    const float* __restrict__ bq)
{
    const int m  = blockIdx.y;
    const int k0 = blockIdx.x * 64;
    const int tid = threadIdx.x;
    const int tk = tid >> 5;   // warp id 0..7 -> k sub-group (warp-uniform)
    const int tc = tid & 31;   // lane        -> c quad

    __shared__ float sAT[32][66];    // [d-chunk][k], pitch 66 (LDS.64-aligned, 2-way STS)
    __shared__ float sW[32][132];    // [d-chunk][c], pitch 132 (LDS.128 conflict-free)

    const float* A  = codebook + ((size_t)m * KC + k0) * DD;
    const float* Wm = wq + (size_t)m * DD * DD;

    unsigned long long acc[4][4];    // [k-pair][c], f32x2 over (k=2p, k=2p+1)
    #pragma unroll
    for (int p = 0; p < 4; p++)
        #pragma unroll
        for (int j = 0; j < 4; j++) acc[p][j] = 0ULL;

    for (int d0 = 0; d0 < DD; d0 += 32) {
        // Load A chunk transposed: sAT[dd][k]. Lane -> dd (coalesced gmem read),
        // STS lanes stride 66 -> 2-way conflict (one-time cost per chunk).
        #pragma unroll
        for (int t = 0; t < 8; t++) {
            int idx = tid + t * 256;       // 0..2047
            int r = idx >> 5, dd = idx & 31;
            sAT[dd][r] = A[r * DD + d0 + dd];
        }
        // Load W chunk: sW[dd][c]. Coalesced gmem read, 4-way STS (one-time).
        #pragma unroll
        for (int t = 0; t < 16; t++) {
            int idx = tid + t * 256;       // 0..4095
            int c = idx >> 5, dd = idx & 31;
            sW[dd][c] = Wm[c * DD + d0 + dd];
        }
        __syncthreads();

        #pragma unroll
        for (int dd = 0; dd < 32; dd++) {
            float4 wv = *reinterpret_cast<const float4*>(&sW[dd][tc * 4]); // LDS.128
            unsigned long long wxx = pack2(wv.x, wv.x);
            unsigned long long wyy = pack2(wv.y, wv.y);
            unsigned long long wzz = pack2(wv.z, wv.z);
            unsigned long long www = pack2(wv.w, wv.w);
            #pragma unroll
            for (int p = 0; p < 4; p++) {
                // broadcast LDS.64: two adjacent k rows at this dd
                unsigned long long aa =
                    *reinterpret_cast<const unsigned long long*>(&sAT[dd][tk * 8 + 2 * p]);
                fma2(acc[p][0], aa, wxx);
                fma2(acc[p][1], aa, wyy);
                fma2(acc[p][2], aa, wzz);
                fma2(acc[p][3], aa, www);
            }
        }
        __syncthreads();
    }

    // Epilogue: add bias, store T tile (STG.128, fully coalesced)
    float4 bias = *reinterpret_cast<const float4*>(&bq[m * DD + tc * 4]);
    float* Tm = g_T + ((size_t)m * KC + k0) * DD;
    #pragma unroll
    for (int p = 0; p < 4; p++) {
        float lo[4], hi[4];
        #pragma unroll
        for (int j = 0; j < 4; j++) unpack2(acc[p][j], lo[j], hi[j]);
        int r = tk * 8 + 2 * p;
        float4 v0, v1;
        v0.x = lo[0] + bias.x; v0.y = lo[1] + bias.y;
        v0.z = lo[2] + bias.z; v0.w = lo[3] + bias.w;
        v1.x = hi[0] + bias.x; v1.y = hi[1] + bias.y;
        v1.z = hi[2] + bias.z; v1.w = hi[3] + bias.w;
        *reinterpret_cast<float4*>(&Tm[(size_t)r * DD + tc * 4]) = v0;
        *reinterpret_cast<float4*>(&Tm[(size_t)(r + 1) * DD + tc * 4]) = v1;
    }
}

// ---------------------------------------------------------------------------
// Phase 2: gather + transpose (vectorized).
// out[n][m*128+c][h][w] = T[m][codes[n][h][w][m]][c]
// grid = (h=64, m=8, n=8), block = 256.
//   gather:  each thread 8x (LDG.128 + STS.128)  (MLP=8, conflict-free)
//   writeout: 8x LDS.128 (conflict-free with pitch 132) + 32x coalesced STG.32
// codes are int32; mask with (KC-1) guards OOB at zero cost.
// ---------------------------------------------------------------------------
__global__ void __launch_bounds__(256, 4) phase2_gather(
    const int* __restrict__ codes,
    float* __restrict__ out)
{
    const int h = blockIdx.x;
    const int m = blockIdx.y;
    const int n = blockIdx.z;
    const int tid  = threadIdx.x;
    const int lane = tid & 31;
    const int wid  = tid >> 5;   // 0..7

    __shared__ float s[64][132];   // [w][c], pitch 132 floats
    __shared__ int scode[64];

    if (tid < 64) {
        scode[tid] = codes[(((size_t)n * HH + h) * WW + tid) * MG + m] & (KC - 1);
    }
    __syncthreads();

    // Gather: warp `wid` loads rows w = wid*8 .. wid*8+7; one LDG.128 per lane
    // per row (32 lanes x 16B = full 512B row). 8 independent loads -> MLP 8.
    const float* Tm = g_T + (size_t)m * KC * DD;
    #pragma unroll
    for (int t = 0; t < 8; t++) {
        int w = wid * 8 + t;
        const float4* Trow = reinterpret_cast<const float4*>(Tm + (size_t)scode[w] * DD);
        float4 v = __ldg(&Trow[lane]);
        *reinterpret_cast<float4*>(&s[w][lane * 4]) = v;
    }
    __syncthreads();

    // Writeout: thread (wlane = tid&63, cq = tid>>6). Per pass reads a float4
    // of 4 consecutive c for its w, then 4 coalesced STG.32 (32 lanes = 32
    // consecutive w = 128B per store).
    const int wlane = tid & 63;
    const int cq    = tid >> 6;   // 0..3
    float* outbase = out + ((((size_t)n * (MG * DD) + m * DD) * HH + h) * WW) + wlane;
    #pragma unroll
    for (int pass = 0; pass < 8; pass++) {
        int c0 = cq * 4 + 16 * pass;
        float4 v = *reinterpret_cast<const float4*>(&s[wlane][c0]);
        outbase[(size_t)(c0 + 0) * HH * WW] = v.x;
        outbase[(size_t)(c0 + 1) * HH * WW] = v.y;
        outbase[(size_t)(c0 + 2) * HH * WW] = v.z;
        outbase[(size_t)(c0 + 3) * HH * WW] = v.w;
    }
}

// ---------------------------------------------------------------------------
// Launch. Inputs (metadata order): codes[int32], codebook[f32], wq[f32], bq[f32]
// ---------------------------------------------------------------------------
extern "C" void kernel_launch(void* const* d_in, const int* in_sizes, int n_in,
                              void* d_out, int out_size) {
    const int*   codes    = (const int*)d_in[0];
    const float* codebook = (const float*)d_in[1];
    const float* wq       = (const float*)d_in[2];
    const float* bq       = (const float*)d_in[3];
    float* out = (float*)d_out;

    dim3 g1(KC / 64, MG);
    phase1_gemm<<<g1, 256>>>(codebook, wq, bq);

    dim3 g2(HH, MG, NB);
    phase2_gather<<<g2, 256>>>(codes, out);
}

// round 5
// speedup vs baseline: 1.1773x; 1.0588x over previous
#include <cuda_runtime.h>
#include <stdint.h>

// Problem constants
#define MG 8      // number of quantizer groups (m)
#define KC 4096   // codebook entries per group
#define DD 128    // dim
#define NB 8      // batch
#define HH 64
#define WW 64

// Scratch: transformed codebook T[m][k][c] = codebook[m][k] @ wq[m]^T + bq[m]
// 8*4096*128 f32 = 16 MB; kept L2-resident via evict_last cache policy.
__device__ float g_T[MG * KC * DD];

// ---- packed fp32x2 helpers ----
__device__ __forceinline__ unsigned long long pack2(float lo, float hi) {
    unsigned long long r;
    asm("mov.b64 %0, {%1, %2};" : "=l"(r) : "f"(lo), "f"(hi));
    return r;
}
__device__ __forceinline__ void unpack2(unsigned long long v, float& lo, float& hi) {
    asm("mov.b64 {%0, %1}, %2;" : "=f"(lo), "=f"(hi) : "l"(v));
}
__device__ __forceinline__ void fma2(unsigned long long& acc,
                                     unsigned long long a,
                                     unsigned long long b) {
    asm("fma.rn.f32x2 %0, %1, %2, %0;" : "+l"(acc) : "l"(a), "l"(b));
}

// ---- L2 cache-policy helpers ----
__device__ __forceinline__ uint64_t make_evict_last_policy() {
    uint64_t pol;
    asm("createpolicy.fractional.L2::evict_last.b64 %0, 1.0;" : "=l"(pol));
    return pol;
}
__device__ __forceinline__ float4 ldg_nc_el(const float4* p, uint64_t pol) {
    float4 v;
    asm volatile("ld.global.nc.L2::cache_hint.v4.f32 {%0,%1,%2,%3}, [%4], %5;"
                 : "=f"(v.x), "=f"(v.y), "=f"(v.z), "=f"(v.w)
                 : "l"(p), "l"(pol));
    return v;
}
__device__ __forceinline__ void stg_el_v4(float* p, float4 v, uint64_t pol) {
    asm volatile("st.global.L2::cache_hint.v4.f32 [%0], {%1,%2,%3,%4}, %5;"
                 :: "l"(p), "f"(v.x), "f"(v.y), "f"(v.z), "f"(v.w), "l"(pol)
                 : "memory");
}
__device__ __forceinline__ void stg_cs(float* p, float v) {
    asm volatile("st.global.cs.f32 [%0], %1;" :: "l"(p), "f"(v) : "memory");
}

// ---------------------------------------------------------------------------
// Phase 1: T[m][k][c] = sum_d codebook[m][k][d] * wq[m][c][d] + bq[m][c]
// grid = (64 k-tiles, 8 m), block = 256, tile 64(k) x 128(c).
// W chunk double-buffered through registers so LDG latency hides under FFMA2.
// T stored with L2 evict_last to prime the cache for phase 2.
// ---------------------------------------------------------------------------
__global__ void __launch_bounds__(256, 4) phase1_gemm(
    const float* __restrict__ codebook,
    const float* __restrict__ wq,
    const float* __restrict__ bq)
{
    const int m  = blockIdx.y;
    const int k0 = blockIdx.x * 64;
    const int tid = threadIdx.x;
    const int tk = tid >> 5;   // warp id -> k sub-group (warp-uniform)
    const int tc = tid & 31;   // lane    -> c quad

    __shared__ float sAT[32][66];    // [d-chunk][k]
    __shared__ float sW[32][132];    // [d-chunk][c]

    const float* A  = codebook + ((size_t)m * KC + k0) * DD;
    const float* Wm = wq + (size_t)m * DD * DD;

    // Per-thread load coords: idx = tid + t*256 -> row = (tid>>5)+8t, dd = tid&31
    const int ar  = tid >> 5;
    const int add = tid & 31;

    unsigned long long acc[4][4];
    #pragma unroll
    for (int p = 0; p < 4; p++)
        #pragma unroll
        for (int j = 0; j < 4; j++) acc[p][j] = 0ULL;

    float rw[16];

    // Prologue: chunk 0
    #pragma unroll
    for (int t = 0; t < 16; t++) rw[t] = Wm[(ar + t * 8) * DD + add];
    #pragma unroll
    for (int t = 0; t < 8; t++) sAT[add][ar + t * 8] = A[(ar + t * 8) * DD + add];
    #pragma unroll
    for (int t = 0; t < 16; t++) sW[add][ar + t * 8] = rw[t];
    __syncthreads();

    #pragma unroll
    for (int ch = 0; ch < 4; ch++) {
        const int d0n = (ch + 1) * 32;
        if (ch < 3) {   // prefetch next W chunk into regs (flies under compute)
            #pragma unroll
            for (int t = 0; t < 16; t++)
                rw[t] = Wm[(ar + t * 8) * DD + d0n + add];
        }

        #pragma unroll
        for (int dd = 0; dd < 32; dd++) {
            float4 wv = *reinterpret_cast<const float4*>(&sW[dd][tc * 4]); // LDS.128
            unsigned long long wxx = pack2(wv.x, wv.x);
            unsigned long long wyy = pack2(wv.y, wv.y);
            unsigned long long wzz = pack2(wv.z, wv.z);
            unsigned long long www = pack2(wv.w, wv.w);
            #pragma unroll
            for (int p = 0; p < 4; p++) {
                unsigned long long aa =
                    *reinterpret_cast<const unsigned long long*>(&sAT[dd][tk * 8 + 2 * p]);
                fma2(acc[p][0], aa, wxx);
                fma2(acc[p][1], aa, wyy);
                fma2(acc[p][2], aa, wzz);
                fma2(acc[p][3], aa, www);
            }
        }
        __syncthreads();

        if (ch < 3) {
            #pragma unroll
            for (int t = 0; t < 8; t++)
                sAT[add][ar + t * 8] = A[(ar + t * 8) * DD + d0n + add];
            #pragma unroll
            for (int t = 0; t < 16; t++) sW[add][ar + t * 8] = rw[t];
            __syncthreads();
        }
    }

    // Epilogue: bias + evict_last stores (prime L2 with T)
    uint64_t pol = make_evict_last_policy();
    float4 bias = *reinterpret_cast<const float4*>(&bq[m * DD + tc * 4]);
    float* Tm = g_T + ((size_t)m * KC + k0) * DD;
    #pragma unroll
    for (int p = 0; p < 4; p++) {
        float lo[4], hi[4];
        #pragma unroll
        for (int j = 0; j < 4; j++) unpack2(acc[p][j], lo[j], hi[j]);
        int r = tk * 8 + 2 * p;
        float4 v0, v1;
        v0.x = lo[0] + bias.x; v0.y = lo[1] + bias.y;
        v0.z = lo[2] + bias.z; v0.w = lo[3] + bias.w;
        v1.x = hi[0] + bias.x; v1.y = hi[1] + bias.y;
        v1.z = hi[2] + bias.z; v1.w = hi[3] + bias.w;
        stg_el_v4(&Tm[(size_t)r * DD + tc * 4], v0, pol);
        stg_el_v4(&Tm[(size_t)(r + 1) * DD + tc * 4], v1, pol);
    }
}

// ---------------------------------------------------------------------------
// Phase 2: gather + transpose.
// out[n][m*128+c][h][w] = T[m][codes[n][h][w][m]][c]
// grid = (h=64, m=8, n=8), block = 256.
// Gather loads use L2 evict_last (keep T resident); output stores use .cs
// (streaming, evict-first) so 134 MB of writes don't thrash T out of L2.
// ---------------------------------------------------------------------------
__global__ void __launch_bounds__(256, 4) phase2_gather(
    const int* __restrict__ codes,
    float* __restrict__ out)
{
    const int h = blockIdx.x;
    const int m = blockIdx.y;
    const int n = blockIdx.z;
    const int tid  = threadIdx.x;
    const int lane = tid & 31;
    const int wid  = tid >> 5;   // 0..7

    __shared__ float s[64][132];   // [w][c]
    __shared__ int scode[64];

    if (tid < 64) {
        scode[tid] = codes[(((size_t)n * HH + h) * WW + tid) * MG + m] & (KC - 1);
    }
    __syncthreads();

    uint64_t pol = make_evict_last_policy();

    // Gather: warp wid loads rows w = wid*8..wid*8+7, one LDG.128 per lane per
    // row (512B/row, MLP=8), L2-pinned via evict_last hint.
    const float* Tm = g_T + (size_t)m * KC * DD;
    #pragma unroll
    for (int t = 0; t < 8; t++) {
        int w = wid * 8 + t;
        const float4* Trow = reinterpret_cast<const float4*>(Tm + (size_t)scode[w] * DD);
        float4 v = ldg_nc_el(&Trow[lane], pol);
        *reinterpret_cast<float4*>(&s[w][lane * 4]) = v;
    }
    __syncthreads();

    // Writeout: thread (wlane = tid&63, cq = tid>>6); LDS.128 then 4 coalesced
    // streaming STG.32 (32 lanes = 128B line, fully covered).
    const int wlane = tid & 63;
    const int cq    = tid >> 6;   // 0..3
    float* outbase = out + ((((size_t)n * (MG * DD) + m * DD) * HH + h) * WW) + wlane;
    #pragma unroll
    for (int pass = 0; pass < 8; pass++) {
        int c0 = cq * 4 + 16 * pass;
        float4 v = *reinterpret_cast<const float4*>(&s[wlane][c0]);
        stg_cs(&outbase[(size_t)(c0 + 0) * HH * WW], v.x);
        stg_cs(&outbase[(size_t)(c0 + 1) * HH * WW], v.y);
        stg_cs(&outbase[(size_t)(c0 + 2) * HH * WW], v.z);
        stg_cs(&outbase[(size_t)(c0 + 3) * HH * WW], v.w);
    }
}

// ---------------------------------------------------------------------------
// Launch. Inputs (metadata order): codes[int32], codebook[f32], wq[f32], bq[f32]
// ---------------------------------------------------------------------------
extern "C" void kernel_launch(void* const* d_in, const int* in_sizes, int n_in,
                              void* d_out, int out_size) {
    const int*   codes    = (const int*)d_in[0];
    const float* codebook = (const float*)d_in[1];
    const float* wq       = (const float*)d_in[2];
    const float* bq       = (const float*)d_in[3];
    float* out = (float*)d_out;

    dim3 g1(KC / 64, MG);
    phase1_gemm<<<g1, 256>>>(codebook, wq, bq);

    dim3 g2(HH, MG, NB);
    phase2_gather<<<g2, 256>>>(codes, out);
}

// round 7
// speedup vs baseline: 1.2135x; 1.0308x over previous
#include <cuda_runtime.h>
#include <stdint.h>

// Problem constants
#define MG 8      // number of quantizer groups (m)
#define KC 4096   // codebook entries per group
#define DD 128    // dim
#define NB 8      // batch
#define HH 64
#define WW 64

// Scratch: transformed codebook T[m][k][c] = codebook[m][k] @ wq[m]^T + bq[m]
__device__ float g_T[MG * KC * DD];

// ---- packed fp32x2 helpers ----
__device__ __forceinline__ unsigned long long pack2(float lo, float hi) {
    unsigned long long r;
    asm("mov.b64 %0, {%1, %2};" : "=l"(r) : "f"(lo), "f"(hi));
    return r;
}
__device__ __forceinline__ void unpack2(unsigned long long v, float& lo, float& hi) {
    asm("mov.b64 {%0, %1}, %2;" : "=f"(lo), "=f"(hi) : "l"(v));
}
__device__ __forceinline__ void fma2(unsigned long long& acc,
                                     unsigned long long a,
                                     unsigned long long b) {
    asm("fma.rn.f32x2 %0, %1, %2, %0;" : "+l"(acc) : "l"(a), "l"(b));
}

// ---- L2 cache-policy helpers ----
__device__ __forceinline__ uint64_t make_evict_last_policy() {
    uint64_t pol;
    asm("createpolicy.fractional.L2::evict_last.b64 %0, 1.0;" : "=l"(pol));
    return pol;
}
__device__ __forceinline__ float4 ldg_nc_el(const float4* p, uint64_t pol) {
    float4 v;
    asm volatile("ld.global.nc.L2::cache_hint.v4.f32 {%0,%1,%2,%3}, [%4], %5;"
                 : "=f"(v.x), "=f"(v.y), "=f"(v.z), "=f"(v.w)
                 : "l"(p), "l"(pol));
    return v;
}
__device__ __forceinline__ void stg_el_v4(float* p, float4 v, uint64_t pol) {
    asm volatile("st.global.L2::cache_hint.v4.f32 [%0], {%1,%2,%3,%4}, %5;"
                 :: "l"(p), "f"(v.x), "f"(v.y), "f"(v.z), "f"(v.w), "l"(pol)
                 : "memory");
}
__device__ __forceinline__ void stg_cs(float* p, float v) {
    asm volatile("st.global.cs.f32 [%0], %1;" :: "l"(p), "f"(v) : "memory");
}

// ---------------------------------------------------------------------------
// Phase 1 (unchanged from the 69.7us version; ~95% of scalar fp32 FFMA peak):
// T[m][k][c] = sum_d codebook[m][k][d]*wq[m][c][d] + bq[m][c]
// grid = (64 k-tiles, 8 m), block = 256, tile 64(k) x 128(c).
// ---------------------------------------------------------------------------
__global__ void __launch_bounds__(256, 4) phase1_gemm(
    const float* __restrict__ codebook,
    const float* __restrict__ wq,
    const float* __restrict__ bq)
{
    const int m  = blockIdx.y;
    const int k0 = blockIdx.x * 64;
    const int tid = threadIdx.x;
    const int tk = tid >> 5;
    const int tc = tid & 31;

    __shared__ float sAT[32][66];
    __shared__ float sW[32][132];

    const float* A  = codebook + ((size_t)m * KC + k0) * DD;
    const float* Wm = wq + (size_t)m * DD * DD;

    const int ar  = tid >> 5;
    const int add = tid & 31;

    unsigned long long acc[4][4];
    #pragma unroll
    for (int p = 0; p < 4; p++)
        #pragma unroll
        for (int j = 0; j < 4; j++) acc[p][j] = 0ULL;

    float rw[16];

    #pragma unroll
    for (int t = 0; t < 16; t++) rw[t] = Wm[(ar + t * 8) * DD + add];
    #pragma unroll
    for (int t = 0; t < 8; t++) sAT[add][ar + t * 8] = A[(ar + t * 8) * DD + add];
    #pragma unroll
    for (int t = 0; t < 16; t++) sW[add][ar + t * 8] = rw[t];
    __syncthreads();

    #pragma unroll
    for (int ch = 0; ch < 4; ch++) {
        const int d0n = (ch + 1) * 32;
        if (ch < 3) {
            #pragma unroll
            for (int t = 0; t < 16; t++)
                rw[t] = Wm[(ar + t * 8) * DD + d0n + add];
        }

        #pragma unroll
        for (int dd = 0; dd < 32; dd++) {
            float4 wv = *reinterpret_cast<const float4*>(&sW[dd][tc * 4]);
            unsigned long long wxx = pack2(wv.x, wv.x);
            unsigned long long wyy = pack2(wv.y, wv.y);
            unsigned long long wzz = pack2(wv.z, wv.z);
            unsigned long long www = pack2(wv.w, wv.w);
            #pragma unroll
            for (int p = 0; p < 4; p++) {
                unsigned long long aa =
                    *reinterpret_cast<const unsigned long long*>(&sAT[dd][tk * 8 + 2 * p]);
                fma2(acc[p][0], aa, wxx);
                fma2(acc[p][1], aa, wyy);
                fma2(acc[p][2], aa, wzz);
                fma2(acc[p][3], aa, www);
            }
        }
        __syncthreads();

        if (ch < 3) {
            #pragma unroll
            for (int t = 0; t < 8; t++)
                sAT[add][ar + t * 8] = A[(ar + t * 8) * DD + d0n + add];
            #pragma unroll
            for (int t = 0; t < 16; t++) sW[add][ar + t * 8] = rw[t];
            __syncthreads();
        }
    }

    uint64_t pol = make_evict_last_policy();
    float4 bias = *reinterpret_cast<const float4*>(&bq[m * DD + tc * 4]);
    float* Tm = g_T + ((size_t)m * KC + k0) * DD;
    #pragma unroll
    for (int p = 0; p < 4; p++) {
        float lo[4], hi[4];
        #pragma unroll
        for (int j = 0; j < 4; j++) unpack2(acc[p][j], lo[j], hi[j]);
        int r = tk * 8 + 2 * p;
        float4 v0, v1;
        v0.x = lo[0] + bias.x; v0.y = lo[1] + bias.y;
        v0.z = lo[2] + bias.z; v0.w = lo[3] + bias.w;
        v1.x = hi[0] + bias.x; v1.y = hi[1] + bias.y;
        v1.z = hi[2] + bias.z; v1.w = hi[3] + bias.w;
        stg_el_v4(&Tm[(size_t)r * DD + tc * 4], v0, pol);
        stg_el_v4(&Tm[(size_t)(r + 1) * DD + tc * 4], v1, pol);
    }
}

// ---------------------------------------------------------------------------
// Phase 2: gather + transpose, 32 tokens per block for high occupancy.
// out[n][m*128+c][h][w] = T[m][codes[n][h][w][m]][c]
// grid = (h-halves=128, m=8, n=8) = 8192 blocks, block = 256.
//   smem 17KB -> 8 blocks/SM (occ ~100%), shorter blocks (smaller tail).
//   gather:  warp wid loads rows w = wid*4..wid*4+3, one LDG.128 per lane/row
//   writeout: thread (w = tid&31, cq = tid>>5); 4 passes of LDS.128 +
//             4 coalesced streaming STG.32 (32 lanes = 128B line).
// ---------------------------------------------------------------------------
__global__ void __launch_bounds__(256, 8) phase2_gather(
    const int* __restrict__ codes,
    float* __restrict__ out)
{
    const int h  = blockIdx.x >> 1;
    const int w0 = (blockIdx.x & 1) * 32;
    const int m  = blockIdx.y;
    const int n  = blockIdx.z;
    const int tid  = threadIdx.x;
    const int lane = tid & 31;
    const int wid  = tid >> 5;   // 0..7

    __shared__ float s[32][132];   // [w][c]
    __shared__ int scode[32];

    if (tid < 32) {
        scode[tid] = codes[(((size_t)n * HH + h) * WW + w0 + tid) * MG + m] & (KC - 1);
    }
    __syncthreads();

    uint64_t pol = make_evict_last_policy();

    // Gather: warp wid handles 4 rows; one LDG.128 per lane per row (512B/row).
    const float* Tm = g_T + (size_t)m * KC * DD;
    #pragma unroll
    for (int t = 0; t < 4; t++) {
        int w = wid * 4 + t;
        const float4* Trow = reinterpret_cast<const float4*>(Tm + (size_t)scode[w] * DD);
        float4 v = ldg_nc_el(&Trow[lane], pol);
        *reinterpret_cast<float4*>(&s[w][lane * 4]) = v;
    }
    __syncthreads();

    // Writeout: w = tid&31, cq = tid>>5 (0..7). Per pass: LDS.128 (4 c for this
    // w), then 4 streaming STG.32; warp = 32 consecutive w = 128B per store.
    const int w  = tid & 31;
    const int cq = tid >> 5;   // 0..7
    float* outbase = out + ((((size_t)n * (MG * DD) + m * DD) * HH + h) * WW) + w0 + w;
    #pragma unroll
    for (int pass = 0; pass < 4; pass++) {
        int c0 = cq * 4 + 32 * pass;
        float4 v = *reinterpret_cast<const float4*>(&s[w][c0]);
        stg_cs(&outbase[(size_t)(c0 + 0) * HH * WW], v.x);
        stg_cs(&outbase[(size_t)(c0 + 1) * HH * WW], v.y);
        stg_cs(&outbase[(size_t)(c0 + 2) * HH * WW], v.z);
        stg_cs(&outbase[(size_t)(c0 + 3) * HH * WW], v.w);
    }
}

// ---------------------------------------------------------------------------
// Launch. Inputs (metadata order): codes[int32], codebook[f32], wq[f32], bq[f32]
// Single stream, two launches (graph-capturable, allocation-free).
// ---------------------------------------------------------------------------
extern "C" void kernel_launch(void* const* d_in, const int* in_sizes, int n_in,
                              void* d_out, int out_size) {
    const int*   codes    = (const int*)d_in[0];
    const float* codebook = (const float*)d_in[1];
    const float* wq       = (const float*)d_in[2];
    const float* bq       = (const float*)d_in[3];
    float* out = (float*)d_out;

    dim3 g1(KC / 64, MG);
    phase1_gemm<<<g1, 256>>>(codebook, wq, bq);

    dim3 g2(HH * 2, MG, NB);
    phase2_gather<<<g2, 256>>>(codes, out);
}

// round 8
// speedup vs baseline: 1.4815x; 1.2208x over previous
#include <cuda_runtime.h>
#include <cuda_bf16.h>
#include <stdint.h>

// Problem constants
#define MG 8      // number of quantizer groups (m)
#define KC 4096   // codebook entries per group
#define DD 128    // dim
#define NB 8      // batch
#define HH 64
#define WW 64

// Scratch: transformed codebook T[m][k][c] = codebook[m][k] @ wq[m]^T + bq[m]
__device__ float g_T[MG * KC * DD];

// ---- L2 cache-policy helpers ----
__device__ __forceinline__ uint64_t make_evict_last_policy() {
    uint64_t pol;
    asm("createpolicy.fractional.L2::evict_last.b64 %0, 1.0;" : "=l"(pol));
    return pol;
}
__device__ __forceinline__ float4 ldg_nc_el(const float4* p, uint64_t pol) {
    float4 v;
    asm volatile("ld.global.nc.L2::cache_hint.v4.f32 {%0,%1,%2,%3}, [%4], %5;"
                 : "=f"(v.x), "=f"(v.y), "=f"(v.z), "=f"(v.w)
                 : "l"(p), "l"(pol));
    return v;
}
__device__ __forceinline__ void stg_el_v2(float* p, float vx, float vy, uint64_t pol) {
    asm volatile("st.global.L2::cache_hint.v2.f32 [%0], {%1,%2}, %3;"
                 :: "l"(p), "f"(vx), "f"(vy), "l"(pol) : "memory");
}
__device__ __forceinline__ void stg_cs(float* p, float v) {
    asm volatile("st.global.cs.f32 [%0], %1;" :: "l"(p), "f"(v) : "memory");
}

// ---- smem / tensor-core helpers ----
__device__ __forceinline__ uint32_t smem_u32(const void* p) {
    uint32_t a;
    asm("{ .reg .u64 t; cvta.to.shared.u64 t, %1; cvt.u32.u64 %0, t; }"
        : "=r"(a) : "l"(p));
    return a;
}
__device__ __forceinline__ uint32_t sw128(uint32_t off) {   // SW128 swizzle
    return off ^ ((off >> 3) & 0x70);
}
__device__ __forceinline__ void ldm_x4(uint32_t* r, uint32_t addr) {
    asm volatile("ldmatrix.sync.aligned.m8n8.x4.shared.b16 {%0,%1,%2,%3}, [%4];"
                 : "=r"(r[0]), "=r"(r[1]), "=r"(r[2]), "=r"(r[3]) : "r"(addr));
}
__device__ __forceinline__ void mma_bf16(float* d, const uint32_t* a, const uint32_t* b) {
    asm volatile("mma.sync.aligned.m16n8k16.row.col.f32.bf16.bf16.f32 "
                 "{%0,%1,%2,%3}, {%4,%5,%6,%7}, {%8,%9}, {%0,%1,%2,%3};"
                 : "+f"(d[0]), "+f"(d[1]), "+f"(d[2]), "+f"(d[3])
                 : "r"(a[0]), "r"(a[1]), "r"(a[2]), "r"(a[3]),
                   "r"(b[0]), "r"(b[1]));
}
// split fp32 pair into packed bf16x2 hi and lo (residual) parts
__device__ __forceinline__ void split2(float x, float y, uint32_t& hi, uint32_t& lo) {
    __nv_bfloat16 hx = __float2bfloat16_rn(x);
    __nv_bfloat16 hy = __float2bfloat16_rn(y);
    float rx = x - __bfloat162float(hx);
    float ry = y - __bfloat162float(hy);
    __nv_bfloat16 lx = __float2bfloat16_rn(rx);
    __nv_bfloat16 ly = __float2bfloat16_rn(ry);
    hi = ((uint32_t)__bfloat16_as_ushort(hy) << 16) | __bfloat16_as_ushort(hx);
    lo = ((uint32_t)__bfloat16_as_ushort(ly) << 16) | __bfloat16_as_ushort(lx);
}

// ---------------------------------------------------------------------------
// Phase 1 (tensor cores, bf16x3 split for ~fp32 accuracy):
// T[m][k][c] = sum_d codebook[m][k][d]*wq[m][c][d] + bq[m][c]
// grid = (64 k-tiles, 8 m), block = 128 (4 warps).
// Block tile 64(k) x 128(c); warp tile 32 x 64; d in two 64-wide chunks.
// A (codebook tile) and B (wq) staged in smem as bf16 hi/lo, SW128 swizzled
// 128B rows -> conflict-free ldmatrix. 3 MMAs per atom: AhBh + AhBl + AlBh.
// ---------------------------------------------------------------------------
__global__ void __launch_bounds__(128, 3) phase1_gemm(
    const float* __restrict__ codebook,
    const float* __restrict__ wq,
    const float* __restrict__ bq)
{
    const int m  = blockIdx.y;
    const int k0 = blockIdx.x * 64;
    const int tid  = threadIdx.x;
    const int lane = tid & 31;
    const int wid  = tid >> 5;      // 0..3
    const int warp_k = wid & 1;     // k strip of 32
    const int warp_c = wid >> 1;    // c strip of 64

    // 48 KB: A_hi[64][64]bf16, A_lo, B_hi[128][64]bf16, B_lo (128B rows, SW128)
    __shared__ __align__(1024) uint8_t smem[49152];
    uint8_t* Ah = smem;
    uint8_t* Al = smem + 8192;
    uint8_t* Bh = smem + 16384;
    uint8_t* Bl = smem + 32768;
    const uint32_t Ah_s = smem_u32(Ah), Al_s = smem_u32(Al);
    const uint32_t Bh_s = smem_u32(Bh), Bl_s = smem_u32(Bl);

    float acc[2][8][4];
    #pragma unroll
    for (int i = 0; i < 2; i++)
        #pragma unroll
        for (int j = 0; j < 8; j++)
            #pragma unroll
            for (int q = 0; q < 4; q++) acc[i][j][q] = 0.f;

    const float* Abase = codebook + ((size_t)m * KC + k0) * DD;
    const float* Bbase = wq + (size_t)m * DD * DD;

    #pragma unroll
    for (int chunk = 0; chunk < 2; chunk++) {
        const int d0 = chunk * 64;
        if (chunk) __syncthreads();   // previous chunk's reads done

        // Stage A: 64 rows x 64 d, fp32 -> bf16 hi/lo, swizzled
        #pragma unroll
        for (int i = 0; i < 8; i++) {
            int e = i * 512 + tid * 4;
            int row = e >> 6, col = e & 63;
            float4 f = *reinterpret_cast<const float4*>(&Abase[row * DD + d0 + col]);
            uint32_t h01, l01, h23, l23;
            split2(f.x, f.y, h01, l01);
            split2(f.z, f.w, h23, l23);
            uint32_t off = sw128(row * 128 + col * 2);
            *reinterpret_cast<uint2*>(Ah + off) = make_uint2(h01, h23);
            *reinterpret_cast<uint2*>(Al + off) = make_uint2(l01, l23);
        }
        // Stage B: 128 c-rows x 64 d
        #pragma unroll
        for (int i = 0; i < 16; i++) {
            int e = i * 512 + tid * 4;
            int row = e >> 6, col = e & 63;
            float4 f = *reinterpret_cast<const float4*>(&Bbase[row * DD + d0 + col]);
            uint32_t h01, l01, h23, l23;
            split2(f.x, f.y, h01, l01);
            split2(f.z, f.w, h23, l23);
            uint32_t off = sw128(row * 128 + col * 2);
            *reinterpret_cast<uint2*>(Bh + off) = make_uint2(h01, h23);
            *reinterpret_cast<uint2*>(Bl + off) = make_uint2(l01, l23);
        }
        __syncthreads();

        #pragma unroll
        for (int ks = 0; ks < 4; ks++) {
            const int kcol = ks * 16;
            // A fragments (2 m-atoms of 16 rows), hi and lo
            uint32_t ah[2][4], al[2][4];
            #pragma unroll
            for (int ma = 0; ma < 2; ma++) {
                int row = warp_k * 32 + ma * 16 + (lane & 7) + ((lane >> 3) & 1) * 8;
                int col = kcol + (lane >> 4) * 8;
                uint32_t off = sw128(row * 128 + col * 2);
                ldm_x4(ah[ma], Ah_s + off);
                ldm_x4(al[ma], Al_s + off);
            }
            // B fragments (8 n-atoms as 4 pairs), hi and lo
            uint32_t bh[8][2], bl[8][2];
            #pragma unroll
            for (int pr = 0; pr < 4; pr++) {
                int row = warp_c * 64 + pr * 16 + (lane & 7) + (lane >> 4) * 8;
                int col = kcol + ((lane >> 3) & 1) * 8;
                uint32_t off = sw128(row * 128 + col * 2);
                uint32_t r[4];
                ldm_x4(r, Bh_s + off);
                bh[2 * pr][0] = r[0]; bh[2 * pr][1] = r[1];
                bh[2 * pr + 1][0] = r[2]; bh[2 * pr + 1][1] = r[3];
                ldm_x4(r, Bl_s + off);
                bl[2 * pr][0] = r[0]; bl[2 * pr][1] = r[1];
                bl[2 * pr + 1][0] = r[2]; bl[2 * pr + 1][1] = r[3];
            }
            // 3-way split MMAs
            #pragma unroll
            for (int ma = 0; ma < 2; ma++)
                #pragma unroll
                for (int na = 0; na < 8; na++) {
                    mma_bf16(acc[ma][na], ah[ma], bh[na]);
                    mma_bf16(acc[ma][na], ah[ma], bl[na]);
                    mma_bf16(acc[ma][na], al[ma], bh[na]);
                }
        }
    }

    // Epilogue: bias + store T (8B stores, quarter-warp = 32B sectors, evict_last)
    uint64_t pol = make_evict_last_policy();
    float* Tm = g_T + ((size_t)m * KC + k0) * DD;
    float2 bias[8];
    #pragma unroll
    for (int na = 0; na < 8; na++) {
        int cg = warp_c * 64 + na * 8 + 2 * (lane & 3);
        bias[na] = make_float2(bq[m * DD + cg], bq[m * DD + cg + 1]);
    }
    #pragma unroll
    for (int ma = 0; ma < 2; ma++) {
        int r0 = k0 * 0 + warp_k * 32 + ma * 16 + (lane >> 2);
        #pragma unroll
        for (int na = 0; na < 8; na++) {
            int cg = warp_c * 64 + na * 8 + 2 * (lane & 3);
            stg_el_v2(&Tm[(size_t)r0 * DD + cg],
                      acc[ma][na][0] + bias[na].x,
                      acc[ma][na][1] + bias[na].y, pol);
            stg_el_v2(&Tm[(size_t)(r0 + 8) * DD + cg],
                      acc[ma][na][2] + bias[na].x,
                      acc[ma][na][3] + bias[na].y, pol);
        }
    }
}

// ---------------------------------------------------------------------------
// Phase 2 (unchanged, 33.8us): gather + transpose, 32 tokens per block.
// out[n][m*128+c][h][w] = T[m][codes[n][h][w][m]][c]
// ---------------------------------------------------------------------------
__global__ void __launch_bounds__(256, 8) phase2_gather(
    const int* __restrict__ codes,
    float* __restrict__ out)
{
    const int h  = blockIdx.x >> 1;
    const int w0 = (blockIdx.x & 1) * 32;
    const int m  = blockIdx.y;
    const int n  = blockIdx.z;
    const int tid  = threadIdx.x;
    const int lane = tid & 31;
    const int wid  = tid >> 5;

    __shared__ float s[32][132];
    __shared__ int scode[32];

    if (tid < 32) {
        scode[tid] = codes[(((size_t)n * HH + h) * WW + w0 + tid) * MG + m] & (KC - 1);
    }
    __syncthreads();

    uint64_t pol = make_evict_last_policy();

    const float* Tm = g_T + (size_t)m * KC * DD;
    #pragma unroll
    for (int t = 0; t < 4; t++) {
        int w = wid * 4 + t;
        const float4* Trow = reinterpret_cast<const float4*>(Tm + (size_t)scode[w] * DD);
        float4 v = ldg_nc_el(&Trow[lane], pol);
        *reinterpret_cast<float4*>(&s[w][lane * 4]) = v;
    }
    __syncthreads();

    const int w  = tid & 31;
    const int cq = tid >> 5;
    float* outbase = out + ((((size_t)n * (MG * DD) + m * DD) * HH + h) * WW) + w0 + w;
    #pragma unroll
    for (int pass = 0; pass < 4; pass++) {
        int c0 = cq * 4 + 32 * pass;
        float4 v = *reinterpret_cast<const float4*>(&s[w][c0]);
        stg_cs(&outbase[(size_t)(c0 + 0) * HH * WW], v.x);
        stg_cs(&outbase[(size_t)(c0 + 1) * HH * WW], v.y);
        stg_cs(&outbase[(size_t)(c0 + 2) * HH * WW], v.z);
        stg_cs(&outbase[(size_t)(c0 + 3) * HH * WW], v.w);
    }
}

// ---------------------------------------------------------------------------
// Launch. Inputs (metadata order): codes[int32], codebook[f32], wq[f32], bq[f32]
// ---------------------------------------------------------------------------
extern "C" void kernel_launch(void* const* d_in, const int* in_sizes, int n_in,
                              void* d_out, int out_size) {
    const int*   codes    = (const int*)d_in[0];
    const float* codebook = (const float*)d_in[1];
    const float* wq       = (const float*)d_in[2];
    const float* bq       = (const float*)d_in[3];
    float* out = (float*)d_out;

    dim3 g1(KC / 64, MG);
    phase1_gemm<<<g1, 128>>>(codebook, wq, bq);

    dim3 g2(HH * 2, MG, NB);
    phase2_gather<<<g2, 256>>>(codes, out);
}

// round 11
// speedup vs baseline: 1.4841x; 1.0017x over previous
#include <cuda_runtime.h>
#include <cuda_bf16.h>
#include <stdint.h>

// Problem constants
#define MG 8      // number of quantizer groups (m)
#define KC 4096   // codebook entries per group
#define DD 128    // dim
#define NB 8      // batch
#define HH 64
#define WW 64

// Scratch: transformed codebook T[m][k][c]
__device__ float g_T[MG * KC * DD];
// Pre-split wq in smem-ready layout: [m][chunk(2)][hi/lo(2)] planes of 16KB.
// Plane = 128 c-rows x 128B (64 d bf16), SW128 swizzled. Total 1 MB.
__device__ __align__(1024) uint8_t g_Wsplit[MG * 2 * 2 * 16384];

// ---- L2 cache-policy helpers ----
__device__ __forceinline__ uint64_t make_evict_last_policy() {
    uint64_t pol;
    asm("createpolicy.fractional.L2::evict_last.b64 %0, 1.0;" : "=l"(pol));
    return pol;
}
__device__ __forceinline__ float4 ldg_nc_el(const float4* p, uint64_t pol) {
    float4 v;
    asm volatile("ld.global.nc.L2::cache_hint.v4.f32 {%0,%1,%2,%3}, [%4], %5;"
                 : "=f"(v.x), "=f"(v.y), "=f"(v.z), "=f"(v.w)
                 : "l"(p), "l"(pol));
    return v;
}
__device__ __forceinline__ void stg_el_v2(float* p, float vx, float vy, uint64_t pol) {
    asm volatile("st.global.L2::cache_hint.v2.f32 [%0], {%1,%2}, %3;"
                 :: "l"(p), "f"(vx), "f"(vy), "l"(pol) : "memory");
}
__device__ __forceinline__ void stg_cs(float* p, float v) {
    asm volatile("st.global.cs.f32 [%0], %1;" :: "l"(p), "f"(v) : "memory");
}

// ---- smem / tensor-core helpers ----
__device__ __forceinline__ uint32_t smem_u32(const void* p) {
    uint32_t a;
    asm("{ .reg .u64 t; cvta.to.shared.u64 t, %1; cvt.u32.u64 %0, t; }"
        : "=r"(a) : "l"(p));
    return a;
}
__device__ __forceinline__ uint32_t sw128(uint32_t off) {   // SW128 swizzle
    return off ^ ((off >> 3) & 0x70);
}
__device__ __forceinline__ void ldm_x4(uint32_t* r, uint32_t addr) {
    asm volatile("ldmatrix.sync.aligned.m8n8.x4.shared.b16 {%0,%1,%2,%3}, [%4];"
                 : "=r"(r[0]), "=r"(r[1]), "=r"(r[2]), "=r"(r[3]) : "r"(addr));
}
__device__ __forceinline__ void mma_bf16(float* d, const uint32_t* a, const uint32_t* b) {
    asm volatile("mma.sync.aligned.m16n8k16.row.col.f32.bf16.bf16.f32 "
                 "{%0,%1,%2,%3}, {%4,%5,%6,%7}, {%8,%9}, {%0,%1,%2,%3};"
                 : "+f"(d[0]), "+f"(d[1]), "+f"(d[2]), "+f"(d[3])
                 : "r"(a[0]), "r"(a[1]), "r"(a[2]), "r"(a[3]),
                   "r"(b[0]), "r"(b[1]));
}
__device__ __forceinline__ void split2(float x, float y, uint32_t& hi, uint32_t& lo) {
    __nv_bfloat16 hx = __float2bfloat16_rn(x);
    __nv_bfloat16 hy = __float2bfloat16_rn(y);
    float rx = x - __bfloat162float(hx);
    float ry = y - __bfloat162float(hy);
    __nv_bfloat16 lx = __float2bfloat16_rn(rx);
    __nv_bfloat16 ly = __float2bfloat16_rn(ry);
    hi = ((uint32_t)__bfloat16_as_ushort(hy) << 16) | __bfloat16_as_ushort(hx);
    lo = ((uint32_t)__bfloat16_as_ushort(ly) << 16) | __bfloat16_as_ushort(lx);
}

// ---------------------------------------------------------------------------
// Prep: split wq into bf16 hi/lo planes, swizzled exactly like phase1's smem B.
// grid = 8 (one per m), block = 256. 16 float4 per thread.
// ---------------------------------------------------------------------------
__global__ void prep_wq(const float* __restrict__ wq) {
    const int m = blockIdx.x;
    const int tid = threadIdx.x;
    const float* Wm = wq + (size_t)m * DD * DD;
    #pragma unroll
    for (int i = 0; i < 16; i++) {
        int e = (i * 256 + tid) * 4;   // element index in [0, 16384)
        int c = e >> 7;                // row 0..127
        int d = e & 127;
        int chunk = d >> 6;
        int dc = d & 63;
        float4 f = *reinterpret_cast<const float4*>(&Wm[c * DD + d]);
        uint32_t h01, l01, h23, l23;
        split2(f.x, f.y, h01, l01);
        split2(f.z, f.w, h23, l23);
        uint32_t off = sw128((uint32_t)(c * 128 + dc * 2));
        uint8_t* hiPlane = g_Wsplit + (((size_t)m * 2 + chunk) * 2 + 0) * 16384;
        uint8_t* loPlane = g_Wsplit + (((size_t)m * 2 + chunk) * 2 + 1) * 16384;
        *reinterpret_cast<uint2*>(hiPlane + off) = make_uint2(h01, h23);
        *reinterpret_cast<uint2*>(loPlane + off) = make_uint2(l01, l23);
    }
}

// ---------------------------------------------------------------------------
// Phase 1 (tensor cores, bf16x3): T[m][k][c] = codebook[m][k] @ wq[m]^T + bq
// grid = (64 k-tiles, 8 m), block = 128 (4 warps), tile 64k x 128c.
// B staged by plain LDG.128->STS.128 copy from pre-split g_Wsplit (no
// conversion; planes byte-identical to the smem layout, L2-hot from prep).
// A chunk1 fp32 prefetched into regs during the prologue.
// NO cp.async anywhere (two rounds of evidence: it traps on this target).
// ---------------------------------------------------------------------------
__global__ void __launch_bounds__(128, 3) phase1_gemm(
    const float* __restrict__ codebook,
    const float* __restrict__ bq)
{
    const int m  = blockIdx.y;
    const int k0 = blockIdx.x * 64;
    const int tid  = threadIdx.x;
    const int lane = tid & 31;
    const int wid  = tid >> 5;      // 0..3
    const int warp_k = wid & 1;     // k strip of 32
    const int warp_c = wid >> 1;    // c strip of 64

    __shared__ __align__(1024) uint8_t smem[49152];
    uint8_t* Ah = smem;             // 8KB: 64 rows x 128B (64 d bf16 hi)
    uint8_t* Al = smem + 8192;      // 8KB
    uint8_t* Bh = smem + 16384;     // 16KB: 128 rows x 128B
    uint8_t* Bl = smem + 32768;     // 16KB
    const uint32_t Ah_s = smem_u32(Ah), Al_s = smem_u32(Al);
    const uint32_t Bh_s = smem_u32(Bh), Bl_s = smem_u32(Bl);

    float acc[2][8][4];
    #pragma unroll
    for (int i = 0; i < 2; i++)
        #pragma unroll
        for (int j = 0; j < 8; j++)
            #pragma unroll
            for (int q = 0; q < 4; q++) acc[i][j][q] = 0.f;

    const float* Abase = codebook + ((size_t)m * KC + k0) * DD;
    // g_Wsplit planes for this m: +0 c0hi, +16384 c0lo, +32768 c1hi, +49152 c1lo
    const uint8_t* Wbase = g_Wsplit + (size_t)m * 4 * 16384;

    // --- prologue ---
    // B chunk0: straight copy (layout already swizzled/split by prep_wq)
    #pragma unroll
    for (int j = 0; j < 8; j++) {
        uint32_t o = (uint32_t)(tid + j * 128) * 16;
        uint4 hv = *reinterpret_cast<const uint4*>(Wbase + o);
        uint4 lv = *reinterpret_cast<const uint4*>(Wbase + 16384 + o);
        *reinterpret_cast<uint4*>(Bh + o) = hv;
        *reinterpret_cast<uint4*>(Bl + o) = lv;
    }
    // A chunk1 prefetch into regs (d 64..127)
    float4 a1[8];
    #pragma unroll
    for (int i = 0; i < 8; i++) {
        int e = i * 512 + tid * 4;
        int row = e >> 6, col = e & 63;
        a1[i] = *reinterpret_cast<const float4*>(&Abase[row * DD + 64 + col]);
    }
    // A chunk0 convert + store (d 0..63)
    #pragma unroll
    for (int i = 0; i < 8; i++) {
        int e = i * 512 + tid * 4;
        int row = e >> 6, col = e & 63;
        float4 f = *reinterpret_cast<const float4*>(&Abase[row * DD + col]);
        uint32_t h01, l01, h23, l23;
        split2(f.x, f.y, h01, l01);
        split2(f.z, f.w, h23, l23);
        uint32_t off = sw128((uint32_t)(row * 128 + col * 2));
        *reinterpret_cast<uint2*>(Ah + off) = make_uint2(h01, h23);
        *reinterpret_cast<uint2*>(Al + off) = make_uint2(l01, l23);
    }
    __syncthreads();

    #pragma unroll
    for (int chunk = 0; chunk < 2; chunk++) {
        #pragma unroll
        for (int ks = 0; ks < 4; ks++) {
            const int kcol = ks * 16;
            uint32_t ah[2][4], al[2][4];
            #pragma unroll
            for (int ma = 0; ma < 2; ma++) {
                int row = warp_k * 32 + ma * 16 + (lane & 7) + ((lane >> 3) & 1) * 8;
                int col = kcol + (lane >> 4) * 8;
                uint32_t off = sw128((uint32_t)(row * 128 + col * 2));
                ldm_x4(ah[ma], Ah_s + off);
                ldm_x4(al[ma], Al_s + off);
            }
            uint32_t bh[8][2], bl[8][2];
            #pragma unroll
            for (int pr = 0; pr < 4; pr++) {
                int row = warp_c * 64 + pr * 16 + (lane & 7) + (lane >> 4) * 8;
                int col = kcol + ((lane >> 3) & 1) * 8;
                uint32_t off = sw128((uint32_t)(row * 128 + col * 2));
                uint32_t r[4];
                ldm_x4(r, Bh_s + off);
                bh[2 * pr][0] = r[0]; bh[2 * pr][1] = r[1];
                bh[2 * pr + 1][0] = r[2]; bh[2 * pr + 1][1] = r[3];
                ldm_x4(r, Bl_s + off);
                bl[2 * pr][0] = r[0]; bl[2 * pr][1] = r[1];
                bl[2 * pr + 1][0] = r[2]; bl[2 * pr + 1][1] = r[3];
            }
            #pragma unroll
            for (int ma = 0; ma < 2; ma++)
                #pragma unroll
                for (int na = 0; na < 8; na++) {
                    mma_bf16(acc[ma][na], ah[ma], bh[na]);
                    mma_bf16(acc[ma][na], ah[ma], bl[na]);
                    mma_bf16(acc[ma][na], al[ma], bh[na]);
                }
        }

        if (chunk == 0) {
            __syncthreads();   // chunk0 smem reads done before overwrite
            // B chunk1: straight copy
            #pragma unroll
            for (int j = 0; j < 8; j++) {
                uint32_t o = (uint32_t)(tid + j * 128) * 16;
                uint4 hv = *reinterpret_cast<const uint4*>(Wbase + 32768 + o);
                uint4 lv = *reinterpret_cast<const uint4*>(Wbase + 49152 + o);
                *reinterpret_cast<uint4*>(Bh + o) = hv;
                *reinterpret_cast<uint4*>(Bl + o) = lv;
            }
            // A chunk1 from prefetched regs
            #pragma unroll
            for (int i = 0; i < 8; i++) {
                int e = i * 512 + tid * 4;
                int row = e >> 6, col = e & 63;
                uint32_t h01, l01, h23, l23;
                split2(a1[i].x, a1[i].y, h01, l01);
                split2(a1[i].z, a1[i].w, h23, l23);
                uint32_t off = sw128((uint32_t)(row * 128 + col * 2));
                *reinterpret_cast<uint2*>(Ah + off) = make_uint2(h01, h23);
                *reinterpret_cast<uint2*>(Al + off) = make_uint2(l01, l23);
            }
            __syncthreads();
        }
    }

    // Epilogue: bias + evict_last T stores
    uint64_t pol = make_evict_last_policy();
    float* Tm = g_T + ((size_t)m * KC + k0) * DD;
    #pragma unroll
    for (int ma = 0; ma < 2; ma++) {
        int r0 = warp_k * 32 + ma * 16 + (lane >> 2);
        #pragma unroll
        for (int na = 0; na < 8; na++) {
            int cg = warp_c * 64 + na * 8 + 2 * (lane & 3);
            float bx = bq[m * DD + cg], by = bq[m * DD + cg + 1];
            stg_el_v2(&Tm[(size_t)r0 * DD + cg],
                      acc[ma][na][0] + bx, acc[ma][na][1] + by, pol);
            stg_el_v2(&Tm[(size_t)(r0 + 8) * DD + cg],
                      acc[ma][na][2] + bx, acc[ma][na][3] + by, pol);
        }
    }
}

// ---------------------------------------------------------------------------
// Phase 2 (verbatim from the R7/R8 passing kernel, 33.8-34.4us):
// gather + transpose, 32 tokens per block.
// out[n][m*128+c][h][w] = T[m][codes[n][h][w][m]][c]
// grid = (h-halves=128, m=8, n=8) = 8192 blocks, block = 256.
// ---------------------------------------------------------------------------
__global__ void __launch_bounds__(256, 8) phase2_gather(
    const int* __restrict__ codes,
    float* __restrict__ out)
{
    const int h  = blockIdx.x >> 1;
    const int w0 = (blockIdx.x & 1) * 32;
    const int m  = blockIdx.y;
    const int n  = blockIdx.z;
    const int tid  = threadIdx.x;
    const int lane = tid & 31;
    const int wid  = tid >> 5;

    __shared__ float s[32][132];
    __shared__ int scode[32];

    if (tid < 32) {
        scode[tid] = codes[(((size_t)n * HH + h) * WW + w0 + tid) * MG + m] & (KC - 1);
    }
    __syncthreads();

    uint64_t pol = make_evict_last_policy();

    const float* Tm = g_T + (size_t)m * KC * DD;
    #pragma unroll
    for (int t = 0; t < 4; t++) {
        int w = wid * 4 + t;
        const float4* Trow = reinterpret_cast<const float4*>(Tm + (size_t)scode[w] * DD);
        float4 v = ldg_nc_el(&Trow[lane], pol);
        *reinterpret_cast<float4*>(&s[w][lane * 4]) = v;
    }
    __syncthreads();

    const int w  = tid & 31;
    const int cq = tid >> 5;
    float* outbase = out + ((((size_t)n * (MG * DD) + m * DD) * HH + h) * WW) + w0 + w;
    #pragma unroll
    for (int pass = 0; pass < 4; pass++) {
        int c0 = cq * 4 + 32 * pass;
        float4 v = *reinterpret_cast<const float4*>(&s[w][c0]);
        stg_cs(&outbase[(size_t)(c0 + 0) * HH * WW], v.x);
        stg_cs(&outbase[(size_t)(c0 + 1) * HH * WW], v.y);
        stg_cs(&outbase[(size_t)(c0 + 2) * HH * WW], v.z);
        stg_cs(&outbase[(size_t)(c0 + 3) * HH * WW], v.w);
    }
}

// ---------------------------------------------------------------------------
// Launch. Inputs (metadata order): codes[int32], codebook[f32], wq[f32], bq[f32]
// ---------------------------------------------------------------------------
extern "C" void kernel_launch(void* const* d_in, const int* in_sizes, int n_in,
                              void* d_out, int out_size) {
    const int*   codes    = (const int*)d_in[0];
    const float* codebook = (const float*)d_in[1];
    const float* wq       = (const float*)d_in[2];
    const float* bq       = (const float*)d_in[3];
    float* out = (float*)d_out;

    prep_wq<<<MG, 256>>>(wq);

    dim3 g1(KC / 64, MG);
    phase1_gemm<<<g1, 128>>>(codebook, bq);

    dim3 g2(HH * 2, MG, NB);
    phase2_gather<<<g2, 256>>>(codes, out);
}

// round 12
// speedup vs baseline: 1.5412x; 1.0385x over previous
#include <cuda_runtime.h>
#include <cuda_bf16.h>
#include <stdint.h>

// Problem constants
#define MG 8      // number of quantizer groups (m)
#define KC 4096   // codebook entries per group
#define DD 128    // dim
#define NB 8      // batch
#define HH 64
#define WW 64

// Scratch: transformed codebook T[m][k][c]
__device__ float g_T[MG * KC * DD];
// Pre-split wq in smem-ready layout: [m][chunk(2)][hi/lo(2)] planes of 16KB.
// Plane = 128 c-rows x 128B (64 d bf16), SW128 swizzled. Total 1 MB.
__device__ __align__(1024) uint8_t g_Wsplit[MG * 2 * 2 * 16384];

// ---- L2 cache-policy helpers ----
__device__ __forceinline__ uint64_t make_evict_last_policy() {
    uint64_t pol;
    asm("createpolicy.fractional.L2::evict_last.b64 %0, 1.0;" : "=l"(pol));
    return pol;
}
__device__ __forceinline__ float4 ldg_nc_el(const float4* p, uint64_t pol) {
    float4 v;
    asm volatile("ld.global.nc.L2::cache_hint.v4.f32 {%0,%1,%2,%3}, [%4], %5;"
                 : "=f"(v.x), "=f"(v.y), "=f"(v.z), "=f"(v.w)
                 : "l"(p), "l"(pol));
    return v;
}
__device__ __forceinline__ void stg_el_v2(float* p, float vx, float vy, uint64_t pol) {
    asm volatile("st.global.L2::cache_hint.v2.f32 [%0], {%1,%2}, %3;"
                 :: "l"(p), "f"(vx), "f"(vy), "l"(pol) : "memory");
}
__device__ __forceinline__ void stg_cs(float* p, float v) {
    asm volatile("st.global.cs.f32 [%0], %1;" :: "l"(p), "f"(v) : "memory");
}

// ---- smem / tensor-core helpers ----
__device__ __forceinline__ uint32_t smem_u32(const void* p) {
    uint32_t a;
    asm("{ .reg .u64 t; cvta.to.shared.u64 t, %1; cvt.u32.u64 %0, t; }"
        : "=r"(a) : "l"(p));
    return a;
}
__device__ __forceinline__ uint32_t sw128(uint32_t off) {   // SW128 swizzle
    return off ^ ((off >> 3) & 0x70);
}
__device__ __forceinline__ void ldm_x4(uint32_t* r, uint32_t addr) {
    asm volatile("ldmatrix.sync.aligned.m8n8.x4.shared.b16 {%0,%1,%2,%3}, [%4];"
                 : "=r"(r[0]), "=r"(r[1]), "=r"(r[2]), "=r"(r[3]) : "r"(addr));
}
__device__ __forceinline__ void mma_bf16(float* d, const uint32_t* a, const uint32_t* b) {
    asm volatile("mma.sync.aligned.m16n8k16.row.col.f32.bf16.bf16.f32 "
                 "{%0,%1,%2,%3}, {%4,%5,%6,%7}, {%8,%9}, {%0,%1,%2,%3};"
                 : "+f"(d[0]), "+f"(d[1]), "+f"(d[2]), "+f"(d[3])
                 : "r"(a[0]), "r"(a[1]), "r"(a[2]), "r"(a[3]),
                   "r"(b[0]), "r"(b[1]));
}
__device__ __forceinline__ void split2(float x, float y, uint32_t& hi, uint32_t& lo) {
    __nv_bfloat16 hx = __float2bfloat16_rn(x);
    __nv_bfloat16 hy = __float2bfloat16_rn(y);
    float rx = x - __bfloat162float(hx);
    float ry = y - __bfloat162float(hy);
    __nv_bfloat16 lx = __float2bfloat16_rn(rx);
    __nv_bfloat16 ly = __float2bfloat16_rn(ry);
    hi = ((uint32_t)__bfloat16_as_ushort(hy) << 16) | __bfloat16_as_ushort(hx);
    lo = ((uint32_t)__bfloat16_as_ushort(ly) << 16) | __bfloat16_as_ushort(lx);
}

// ---------------------------------------------------------------------------
// Prep: split wq into bf16 hi/lo planes, swizzled exactly like phase1's smem B.
// grid = (8 slices, 8 m) = 64 blocks (R10 used 8 blocks -> 6.9us of pure
// latency on 8 SMs; same work spread 8x wider). 2 float4 per thread.
// ---------------------------------------------------------------------------
__global__ void prep_wq(const float* __restrict__ wq) {
    const int slice = blockIdx.x;   // 0..7
    const int m     = blockIdx.y;   // 0..7
    const int tid   = threadIdx.x;
    const float* Wm = wq + (size_t)m * DD * DD;
    #pragma unroll
    for (int i = 0; i < 2; i++) {
        int e = ((slice * 2 + i) * 256 + tid) * 4;   // element index in [0, 16384)
        int c = e >> 7;                // row 0..127
        int d = e & 127;
        int chunk = d >> 6;
        int dc = d & 63;
        float4 f = *reinterpret_cast<const float4*>(&Wm[c * DD + d]);
        uint32_t h01, l01, h23, l23;
        split2(f.x, f.y, h01, l01);
        split2(f.z, f.w, h23, l23);
        uint32_t off = sw128((uint32_t)(c * 128 + dc * 2));
        uint8_t* hiPlane = g_Wsplit + (((size_t)m * 2 + chunk) * 2 + 0) * 16384;
        uint8_t* loPlane = g_Wsplit + (((size_t)m * 2 + chunk) * 2 + 1) * 16384;
        *reinterpret_cast<uint2*>(hiPlane + off) = make_uint2(h01, h23);
        *reinterpret_cast<uint2*>(loPlane + off) = make_uint2(l01, l23);
    }
}

// ---------------------------------------------------------------------------
// Phase 1 (tensor cores, bf16x3): T[m][k][c] = codebook[m][k] @ wq[m]^T + bq
// grid = (64 k-tiles, 8 m), block = 128 (4 warps), tile 64k x 128c.
// B staged by plain LDG.128->STS.128 copy from pre-split g_Wsplit.
// A chunk1 fp32 prefetched into regs during the prologue. (~14us measured)
// ---------------------------------------------------------------------------
__global__ void __launch_bounds__(128, 3) phase1_gemm(
    const float* __restrict__ codebook,
    const float* __restrict__ bq)
{
    const int m  = blockIdx.y;
    const int k0 = blockIdx.x * 64;
    const int tid  = threadIdx.x;
    const int lane = tid & 31;
    const int wid  = tid >> 5;      // 0..3
    const int warp_k = wid & 1;     // k strip of 32
    const int warp_c = wid >> 1;    // c strip of 64

    __shared__ __align__(1024) uint8_t smem[49152];
    uint8_t* Ah = smem;             // 8KB: 64 rows x 128B (64 d bf16 hi)
    uint8_t* Al = smem + 8192;      // 8KB
    uint8_t* Bh = smem + 16384;     // 16KB: 128 rows x 128B
    uint8_t* Bl = smem + 32768;     // 16KB
    const uint32_t Ah_s = smem_u32(Ah), Al_s = smem_u32(Al);
    const uint32_t Bh_s = smem_u32(Bh), Bl_s = smem_u32(Bl);

    float acc[2][8][4];
    #pragma unroll
    for (int i = 0; i < 2; i++)
        #pragma unroll
        for (int j = 0; j < 8; j++)
            #pragma unroll
            for (int q = 0; q < 4; q++) acc[i][j][q] = 0.f;

    const float* Abase = codebook + ((size_t)m * KC + k0) * DD;
    // g_Wsplit planes for this m: +0 c0hi, +16384 c0lo, +32768 c1hi, +49152 c1lo
    const uint8_t* Wbase = g_Wsplit + (size_t)m * 4 * 16384;

    // --- prologue ---
    // B chunk0: straight copy (layout already swizzled/split by prep_wq)
    #pragma unroll
    for (int j = 0; j < 8; j++) {
        uint32_t o = (uint32_t)(tid + j * 128) * 16;
        uint4 hv = *reinterpret_cast<const uint4*>(Wbase + o);
        uint4 lv = *reinterpret_cast<const uint4*>(Wbase + 16384 + o);
        *reinterpret_cast<uint4*>(Bh + o) = hv;
        *reinterpret_cast<uint4*>(Bl + o) = lv;
    }
    // A chunk1 prefetch into regs (d 64..127)
    float4 a1[8];
    #pragma unroll
    for (int i = 0; i < 8; i++) {
        int e = i * 512 + tid * 4;
        int row = e >> 6, col = e & 63;
        a1[i] = *reinterpret_cast<const float4*>(&Abase[row * DD + 64 + col]);
    }
    // A chunk0 convert + store (d 0..63)
    #pragma unroll
    for (int i = 0; i < 8; i++) {
        int e = i * 512 + tid * 4;
        int row = e >> 6, col = e & 63;
        float4 f = *reinterpret_cast<const float4*>(&Abase[row * DD + col]);
        uint32_t h01, l01, h23, l23;
        split2(f.x, f.y, h01, l01);
        split2(f.z, f.w, h23, l23);
        uint32_t off = sw128((uint32_t)(row * 128 + col * 2));
        *reinterpret_cast<uint2*>(Ah + off) = make_uint2(h01, h23);
        *reinterpret_cast<uint2*>(Al + off) = make_uint2(l01, l23);
    }
    __syncthreads();

    #pragma unroll
    for (int chunk = 0; chunk < 2; chunk++) {
        #pragma unroll
        for (int ks = 0; ks < 4; ks++) {
            const int kcol = ks * 16;
            uint32_t ah[2][4], al[2][4];
            #pragma unroll
            for (int ma = 0; ma < 2; ma++) {
                int row = warp_k * 32 + ma * 16 + (lane & 7) + ((lane >> 3) & 1) * 8;
                int col = kcol + (lane >> 4) * 8;
                uint32_t off = sw128((uint32_t)(row * 128 + col * 2));
                ldm_x4(ah[ma], Ah_s + off);
                ldm_x4(al[ma], Al_s + off);
            }
            uint32_t bh[8][2], bl[8][2];
            #pragma unroll
            for (int pr = 0; pr < 4; pr++) {
                int row = warp_c * 64 + pr * 16 + (lane & 7) + (lane >> 4) * 8;
                int col = kcol + ((lane >> 3) & 1) * 8;
                uint32_t off = sw128((uint32_t)(row * 128 + col * 2));
                uint32_t r[4];
                ldm_x4(r, Bh_s + off);
                bh[2 * pr][0] = r[0]; bh[2 * pr][1] = r[1];
                bh[2 * pr + 1][0] = r[2]; bh[2 * pr + 1][1] = r[3];
                ldm_x4(r, Bl_s + off);
                bl[2 * pr][0] = r[0]; bl[2 * pr][1] = r[1];
                bl[2 * pr + 1][0] = r[2]; bl[2 * pr + 1][1] = r[3];
            }
            #pragma unroll
            for (int ma = 0; ma < 2; ma++)
                #pragma unroll
                for (int na = 0; na < 8; na++) {
                    mma_bf16(acc[ma][na], ah[ma], bh[na]);
                    mma_bf16(acc[ma][na], ah[ma], bl[na]);
                    mma_bf16(acc[ma][na], al[ma], bh[na]);
                }
        }

        if (chunk == 0) {
            __syncthreads();   // chunk0 smem reads done before overwrite
            // B chunk1: straight copy
            #pragma unroll
            for (int j = 0; j < 8; j++) {
                uint32_t o = (uint32_t)(tid + j * 128) * 16;
                uint4 hv = *reinterpret_cast<const uint4*>(Wbase + 32768 + o);
                uint4 lv = *reinterpret_cast<const uint4*>(Wbase + 49152 + o);
                *reinterpret_cast<uint4*>(Bh + o) = hv;
                *reinterpret_cast<uint4*>(Bl + o) = lv;
            }
            // A chunk1 from prefetched regs
            #pragma unroll
            for (int i = 0; i < 8; i++) {
                int e = i * 512 + tid * 4;
                int row = e >> 6, col = e & 63;
                uint32_t h01, l01, h23, l23;
                split2(a1[i].x, a1[i].y, h01, l01);
                split2(a1[i].z, a1[i].w, h23, l23);
                uint32_t off = sw128((uint32_t)(row * 128 + col * 2));
                *reinterpret_cast<uint2*>(Ah + off) = make_uint2(h01, h23);
                *reinterpret_cast<uint2*>(Al + off) = make_uint2(l01, l23);
            }
            __syncthreads();
        }
    }

    // Epilogue: bias + evict_last T stores
    uint64_t pol = make_evict_last_policy();
    float* Tm = g_T + ((size_t)m * KC + k0) * DD;
    #pragma unroll
    for (int ma = 0; ma < 2; ma++) {
        int r0 = warp_k * 32 + ma * 16 + (lane >> 2);
        #pragma unroll
        for (int na = 0; na < 8; na++) {
            int cg = warp_c * 64 + na * 8 + 2 * (lane & 3);
            float bx = bq[m * DD + cg], by = bq[m * DD + cg + 1];
            stg_el_v2(&Tm[(size_t)r0 * DD + cg],
                      acc[ma][na][0] + bx, acc[ma][na][1] + by, pol);
            stg_el_v2(&Tm[(size_t)(r0 + 8) * DD + cg],
                      acc[ma][na][2] + bx, acc[ma][na][3] + by, pol);
        }
    }
}

// ---------------------------------------------------------------------------
// Phase 2 (verbatim, proven 33.8-34.4us): gather + transpose, 32 tokens/block.
// out[n][m*128+c][h][w] = T[m][codes[n][h][w][m]][c]
// grid = (h-halves=128, m=8, n=8) = 8192 blocks, block = 256.
// ---------------------------------------------------------------------------
__global__ void __launch_bounds__(256, 8) phase2_gather(
    const int* __restrict__ codes,
    float* __restrict__ out)
{
    const int h  = blockIdx.x >> 1;
    const int w0 = (blockIdx.x & 1) * 32;
    const int m  = blockIdx.y;
    const int n  = blockIdx.z;
    const int tid  = threadIdx.x;
    const int lane = tid & 31;
    const int wid  = tid >> 5;

    __shared__ float s[32][132];
    __shared__ int scode[32];

    if (tid < 32) {
        scode[tid] = codes[(((size_t)n * HH + h) * WW + w0 + tid) * MG + m] & (KC - 1);
    }
    __syncthreads();

    uint64_t pol = make_evict_last_policy();

    const float* Tm = g_T + (size_t)m * KC * DD;
    #pragma unroll
    for (int t = 0; t < 4; t++) {
        int w = wid * 4 + t;
        const float4* Trow = reinterpret_cast<const float4*>(Tm + (size_t)scode[w] * DD);
        float4 v = ldg_nc_el(&Trow[lane], pol);
        *reinterpret_cast<float4*>(&s[w][lane * 4]) = v;
    }
    __syncthreads();

    const int w  = tid & 31;
    const int cq = tid >> 5;
    float* outbase = out + ((((size_t)n * (MG * DD) + m * DD) * HH + h) * WW) + w0 + w;
    #pragma unroll
    for (int pass = 0; pass < 4; pass++) {
        int c0 = cq * 4 + 32 * pass;
        float4 v = *reinterpret_cast<const float4*>(&s[w][c0]);
        stg_cs(&outbase[(size_t)(c0 + 0) * HH * WW], v.x);
        stg_cs(&outbase[(size_t)(c0 + 1) * HH * WW], v.y);
        stg_cs(&outbase[(size_t)(c0 + 2) * HH * WW], v.z);
        stg_cs(&outbase[(size_t)(c0 + 3) * HH * WW], v.w);
    }
}

// ---------------------------------------------------------------------------
// Launch. Inputs (metadata order): codes[int32], codebook[f32], wq[f32], bq[f32]
// ---------------------------------------------------------------------------
extern "C" void kernel_launch(void* const* d_in, const int* in_sizes, int n_in,
                              void* d_out, int out_size) {
    const int*   codes    = (const int*)d_in[0];
    const float* codebook = (const float*)d_in[1];
    const float* wq       = (const float*)d_in[2];
    const float* bq       = (const float*)d_in[3];
    float* out = (float*)d_out;

    dim3 gp(8, MG);
    prep_wq<<<gp, 256>>>(wq);

    dim3 g1(KC / 64, MG);
    phase1_gemm<<<g1, 128>>>(codebook, bq);

    dim3 g2(HH * 2, MG, NB);
    phase2_gather<<<g2, 256>>>(codes, out);
}

// round 13
// speedup vs baseline: 1.6568x; 1.0750x over previous
#include <cuda_runtime.h>
#include <cuda_bf16.h>
#include <stdint.h>

// Problem constants
#define MG 8      // number of quantizer groups (m)
#define KC 4096   // codebook entries per group
#define DD 128    // dim
#define NB 8      // batch
#define HH 64
#define WW 64

// Scratch: transformed codebook T[m][k][c]
__device__ float g_T[MG * KC * DD];
// Pre-split wq in smem-ready layout: [m][chunk(2)][hi/lo(2)] planes of 16KB.
__device__ __align__(1024) uint8_t g_Wsplit[MG * 2 * 2 * 16384];

// ---- L2 cache-policy helpers ----
__device__ __forceinline__ uint64_t make_evict_last_policy() {
    uint64_t pol;
    asm("createpolicy.fractional.L2::evict_last.b64 %0, 1.0;" : "=l"(pol));
    return pol;
}
__device__ __forceinline__ float4 ldg_nc_el(const float4* p, uint64_t pol) {
    float4 v;
    asm volatile("ld.global.nc.L2::cache_hint.v4.f32 {%0,%1,%2,%3}, [%4], %5;"
                 : "=f"(v.x), "=f"(v.y), "=f"(v.z), "=f"(v.w)
                 : "l"(p), "l"(pol));
    return v;
}
__device__ __forceinline__ void stg_el_v2(float* p, float vx, float vy, uint64_t pol) {
    asm volatile("st.global.L2::cache_hint.v2.f32 [%0], {%1,%2}, %3;"
                 :: "l"(p), "f"(vx), "f"(vy), "l"(pol) : "memory");
}
__device__ __forceinline__ void stg_cs(float* p, float v) {
    asm volatile("st.global.cs.f32 [%0], %1;" :: "l"(p), "f"(v) : "memory");
}

// ---- smem / tensor-core helpers ----
__device__ __forceinline__ uint32_t smem_u32(const void* p) {
    uint32_t a;
    asm("{ .reg .u64 t; cvta.to.shared.u64 t, %1; cvt.u32.u64 %0, t; }"
        : "=r"(a) : "l"(p));
    return a;
}
__device__ __forceinline__ uint32_t sw128(uint32_t off) {   // SW128 swizzle
    return off ^ ((off >> 3) & 0x70);
}
__device__ __forceinline__ void ldm_x4(uint32_t* r, uint32_t addr) {
    asm volatile("ldmatrix.sync.aligned.m8n8.x4.shared.b16 {%0,%1,%2,%3}, [%4];"
                 : "=r"(r[0]), "=r"(r[1]), "=r"(r[2]), "=r"(r[3]) : "r"(addr));
}
__device__ __forceinline__ void mma_bf16(float* d, const uint32_t* a, const uint32_t* b) {
    asm volatile("mma.sync.aligned.m16n8k16.row.col.f32.bf16.bf16.f32 "
                 "{%0,%1,%2,%3}, {%4,%5,%6,%7}, {%8,%9}, {%0,%1,%2,%3};"
                 : "+f"(d[0]), "+f"(d[1]), "+f"(d[2]), "+f"(d[3])
                 : "r"(a[0]), "r"(a[1]), "r"(a[2]), "r"(a[3]),
                   "r"(b[0]), "r"(b[1]));
}
__device__ __forceinline__ void split2(float x, float y, uint32_t& hi, uint32_t& lo) {
    __nv_bfloat16 hx = __float2bfloat16_rn(x);
    __nv_bfloat16 hy = __float2bfloat16_rn(y);
    float rx = x - __bfloat162float(hx);
    float ry = y - __bfloat162float(hy);
    __nv_bfloat16 lx = __float2bfloat16_rn(rx);
    __nv_bfloat16 ly = __float2bfloat16_rn(ry);
    hi = ((uint32_t)__bfloat16_as_ushort(hy) << 16) | __bfloat16_as_ushort(hx);
    lo = ((uint32_t)__bfloat16_as_ushort(ly) << 16) | __bfloat16_as_ushort(lx);
}

// ---------------------------------------------------------------------------
// Prep: split wq into bf16 hi/lo planes, swizzled like phase1's smem B.
// grid = (16 slices, 8 m) = 128 blocks, 1 float4 per thread.
// ---------------------------------------------------------------------------
__global__ void prep_wq(const float* __restrict__ wq) {
    const int slice = blockIdx.x;   // 0..15
    const int m     = blockIdx.y;   // 0..7
    const int tid   = threadIdx.x;
    const float* Wm = wq + (size_t)m * DD * DD;

    int e = (slice * 256 + tid) * 4;   // element index in [0, 16384)
    int c = e >> 7;                    // row 0..127
    int d = e & 127;
    int chunk = d >> 6;
    int dc = d & 63;
    float4 f = *reinterpret_cast<const float4*>(&Wm[c * DD + d]);
    uint32_t h01, l01, h23, l23;
    split2(f.x, f.y, h01, l01);
    split2(f.z, f.w, h23, l23);
    uint32_t off = sw128((uint32_t)(c * 128 + dc * 2));
    uint8_t* hiPlane = g_Wsplit + (((size_t)m * 2 + chunk) * 2 + 0) * 16384;
    uint8_t* loPlane = g_Wsplit + (((size_t)m * 2 + chunk) * 2 + 1) * 16384;
    *reinterpret_cast<uint2*>(hiPlane + off) = make_uint2(h01, h23);
    *reinterpret_cast<uint2*>(loPlane + off) = make_uint2(l01, l23);
}

// ---------------------------------------------------------------------------
// Phase 1 (unchanged, ~14.5us): T[m][k][c] = codebook[m][k] @ wq[m]^T + bq
// grid = (64 k-tiles, 8 m), block = 128 (4 warps), tile 64k x 128c, bf16x3.
// ---------------------------------------------------------------------------
__global__ void __launch_bounds__(128, 3) phase1_gemm(
    const float* __restrict__ codebook,
    const float* __restrict__ bq)
{
    const int m  = blockIdx.y;
    const int k0 = blockIdx.x * 64;
    const int tid  = threadIdx.x;
    const int lane = tid & 31;
    const int wid  = tid >> 5;      // 0..3
    const int warp_k = wid & 1;     // k strip of 32
    const int warp_c = wid >> 1;    // c strip of 64

    __shared__ __align__(1024) uint8_t smem[49152];
    uint8_t* Ah = smem;
    uint8_t* Al = smem + 8192;
    uint8_t* Bh = smem + 16384;
    uint8_t* Bl = smem + 32768;
    const uint32_t Ah_s = smem_u32(Ah), Al_s = smem_u32(Al);
    const uint32_t Bh_s = smem_u32(Bh), Bl_s = smem_u32(Bl);

    float acc[2][8][4];
    #pragma unroll
    for (int i = 0; i < 2; i++)
        #pragma unroll
        for (int j = 0; j < 8; j++)
            #pragma unroll
            for (int q = 0; q < 4; q++) acc[i][j][q] = 0.f;

    const float* Abase = codebook + ((size_t)m * KC + k0) * DD;
    const uint8_t* Wbase = g_Wsplit + (size_t)m * 4 * 16384;

    // --- prologue ---
    #pragma unroll
    for (int j = 0; j < 8; j++) {
        uint32_t o = (uint32_t)(tid + j * 128) * 16;
        uint4 hv = *reinterpret_cast<const uint4*>(Wbase + o);
        uint4 lv = *reinterpret_cast<const uint4*>(Wbase + 16384 + o);
        *reinterpret_cast<uint4*>(Bh + o) = hv;
        *reinterpret_cast<uint4*>(Bl + o) = lv;
    }
    float4 a1[8];
    #pragma unroll
    for (int i = 0; i < 8; i++) {
        int e = i * 512 + tid * 4;
        int row = e >> 6, col = e & 63;
        a1[i] = *reinterpret_cast<const float4*>(&Abase[row * DD + 64 + col]);
    }
    #pragma unroll
    for (int i = 0; i < 8; i++) {
        int e = i * 512 + tid * 4;
        int row = e >> 6, col = e & 63;
        float4 f = *reinterpret_cast<const float4*>(&Abase[row * DD + col]);
        uint32_t h01, l01, h23, l23;
        split2(f.x, f.y, h01, l01);
        split2(f.z, f.w, h23, l23);
        uint32_t off = sw128((uint32_t)(row * 128 + col * 2));
        *reinterpret_cast<uint2*>(Ah + off) = make_uint2(h01, h23);
        *reinterpret_cast<uint2*>(Al + off) = make_uint2(l01, l23);
    }
    __syncthreads();

    #pragma unroll
    for (int chunk = 0; chunk < 2; chunk++) {
        #pragma unroll
        for (int ks = 0; ks < 4; ks++) {
            const int kcol = ks * 16;
            uint32_t ah[2][4], al[2][4];
            #pragma unroll
            for (int ma = 0; ma < 2; ma++) {
                int row = warp_k * 32 + ma * 16 + (lane & 7) + ((lane >> 3) & 1) * 8;
                int col = kcol + (lane >> 4) * 8;
                uint32_t off = sw128((uint32_t)(row * 128 + col * 2));
                ldm_x4(ah[ma], Ah_s + off);
                ldm_x4(al[ma], Al_s + off);
            }
            uint32_t bh[8][2], bl[8][2];
            #pragma unroll
            for (int pr = 0; pr < 4; pr++) {
                int row = warp_c * 64 + pr * 16 + (lane & 7) + (lane >> 4) * 8;
                int col = kcol + ((lane >> 3) & 1) * 8;
                uint32_t off = sw128((uint32_t)(row * 128 + col * 2));
                uint32_t r[4];
                ldm_x4(r, Bh_s + off);
                bh[2 * pr][0] = r[0]; bh[2 * pr][1] = r[1];
                bh[2 * pr + 1][0] = r[2]; bh[2 * pr + 1][1] = r[3];
                ldm_x4(r, Bl_s + off);
                bl[2 * pr][0] = r[0]; bl[2 * pr][1] = r[1];
                bl[2 * pr + 1][0] = r[2]; bl[2 * pr + 1][1] = r[3];
            }
            #pragma unroll
            for (int ma = 0; ma < 2; ma++)
                #pragma unroll
                for (int na = 0; na < 8; na++) {
                    mma_bf16(acc[ma][na], ah[ma], bh[na]);
                    mma_bf16(acc[ma][na], ah[ma], bl[na]);
                    mma_bf16(acc[ma][na], al[ma], bh[na]);
                }
        }

        if (chunk == 0) {
            __syncthreads();
            #pragma unroll
            for (int j = 0; j < 8; j++) {
                uint32_t o = (uint32_t)(tid + j * 128) * 16;
                uint4 hv = *reinterpret_cast<const uint4*>(Wbase + 32768 + o);
                uint4 lv = *reinterpret_cast<const uint4*>(Wbase + 49152 + o);
                *reinterpret_cast<uint4*>(Bh + o) = hv;
                *reinterpret_cast<uint4*>(Bl + o) = lv;
            }
            #pragma unroll
            for (int i = 0; i < 8; i++) {
                int e = i * 512 + tid * 4;
                int row = e >> 6, col = e & 63;
                uint32_t h01, l01, h23, l23;
                split2(a1[i].x, a1[i].y, h01, l01);
                split2(a1[i].z, a1[i].w, h23, l23);
                uint32_t off = sw128((uint32_t)(row * 128 + col * 2));
                *reinterpret_cast<uint2*>(Ah + off) = make_uint2(h01, h23);
                *reinterpret_cast<uint2*>(Al + off) = make_uint2(l01, l23);
            }
            __syncthreads();
        }
    }

    uint64_t pol = make_evict_last_policy();
    float* Tm = g_T + ((size_t)m * KC + k0) * DD;
    #pragma unroll
    for (int ma = 0; ma < 2; ma++) {
        int r0 = warp_k * 32 + ma * 16 + (lane >> 2);
        #pragma unroll
        for (int na = 0; na < 8; na++) {
            int cg = warp_c * 64 + na * 8 + 2 * (lane & 3);
            float bx = bq[m * DD + cg], by = bq[m * DD + cg + 1];
            stg_el_v2(&Tm[(size_t)r0 * DD + cg],
                      acc[ma][na][0] + bx, acc[ma][na][1] + by, pol);
            stg_el_v2(&Tm[(size_t)(r0 + 8) * DD + cg],
                      acc[ma][na][2] + bx, acc[ma][na][3] + by, pol);
        }
    }
}

// ---------------------------------------------------------------------------
// Phase 2 (m-fused, software-pipelined): each block handles 32 tokens for ALL
// 8 m-groups. grid = (h-halves=128, n=8) = 1024 blocks (~all resident, ~1
// wave), block = 256, smem 34KB -> 6 blocks/SM.
// Pipeline per m: STS(m) -> sync -> LDG(m+1) gather (flies under writeout) ->
// writeout(m). Double buffer => one sync per iteration.
// ---------------------------------------------------------------------------
__global__ void __launch_bounds__(256, 6) phase2_gather(
    const int* __restrict__ codes,
    float* __restrict__ out)
{
    const int h  = blockIdx.x >> 1;
    const int w0 = (blockIdx.x & 1) * 32;
    const int n  = blockIdx.y;
    const int tid  = threadIdx.x;
    const int lane = tid & 31;
    const int wid  = tid >> 5;   // 0..7

    __shared__ float s[2][32][132];
    __shared__ int scode[32][8];

    // All codes for these 32 tokens x 8 m: 256 consecutive int32 (coalesced)
    {
        int w = tid >> 3, mm = tid & 7;
        scode[w][mm] = codes[(((size_t)n * HH + h) * WW + w0 + w) * MG + mm] & (KC - 1);
    }
    __syncthreads();

    uint64_t pol = make_evict_last_policy();

    // Gather coords: warp wid covers rows w = wid*4..wid*4+3; lane = 16B chunk.
    float4 g[4];
    #pragma unroll
    for (int t = 0; t < 4; t++) {
        int w = wid * 4 + t;
        const float4* row = reinterpret_cast<const float4*>(
            g_T + (size_t)scode[w][0] * DD);
        g[t] = ldg_nc_el(row + lane, pol);
    }

    const int wl = tid & 31;
    const int cq = tid >> 5;   // 0..7

    #pragma unroll
    for (int mm = 0; mm < MG; mm++) {
        const int st = mm & 1;
        // stage gathered rows into this m's buffer
        #pragma unroll
        for (int t = 0; t < 4; t++) {
            int w = wid * 4 + t;
            *reinterpret_cast<float4*>(&s[st][w][lane * 4]) = g[t];
        }
        __syncthreads();

        // issue next m's gather; latency hides under the writeout below
        if (mm < MG - 1) {
            const float* Tn = g_T + (size_t)(mm + 1) * KC * DD;
            #pragma unroll
            for (int t = 0; t < 4; t++) {
                int w = wid * 4 + t;
                const float4* row = reinterpret_cast<const float4*>(
                    Tn + (size_t)scode[w][mm + 1] * DD);
                g[t] = ldg_nc_el(row + lane, pol);
            }
        }

        // writeout m: thread (wl, cq); 4 passes LDS.128 + 4 streaming STG.32
        float* outbase = out +
            ((((size_t)n * (MG * DD) + mm * DD) * HH + h) * WW) + w0 + wl;
        #pragma unroll
        for (int pass = 0; pass < 4; pass++) {
            int c0 = cq * 4 + 32 * pass;
            float4 v = *reinterpret_cast<const float4*>(&s[st][wl][c0]);
            stg_cs(&outbase[(size_t)(c0 + 0) * HH * WW], v.x);
            stg_cs(&outbase[(size_t)(c0 + 1) * HH * WW], v.y);
            stg_cs(&outbase[(size_t)(c0 + 2) * HH * WW], v.z);
            stg_cs(&outbase[(size_t)(c0 + 3) * HH * WW], v.w);
        }
        // no second sync: double buffer; next iter's STS targets s[st^1],
        // and the sync at the top of the next iteration orders buffer reuse.
    }
}

// ---------------------------------------------------------------------------
// Launch. Inputs (metadata order): codes[int32], codebook[f32], wq[f32], bq[f32]
// ---------------------------------------------------------------------------
extern "C" void kernel_launch(void* const* d_in, const int* in_sizes, int n_in,
                              void* d_out, int out_size) {
    const int*   codes    = (const int*)d_in[0];
    const float* codebook = (const float*)d_in[1];
    const float* wq       = (const float*)d_in[2];
    const float* bq       = (const float*)d_in[3];
    float* out = (float*)d_out;

    dim3 gp(16, MG);
    prep_wq<<<gp, 256>>>(wq);

    dim3 g1(KC / 64, MG);
    phase1_gemm<<<g1, 128>>>(codebook, bq);

    dim3 g2(HH * 2, NB);
    phase2_gather<<<g2, 256>>>(codes, out);
}

// round 14
// speedup vs baseline: 1.6697x; 1.0078x over previous
#include <cuda_runtime.h>
#include <cuda_bf16.h>
#include <stdint.h>

// Problem constants
#define MG 8      // number of quantizer groups (m)
#define KC 4096   // codebook entries per group
#define DD 128    // dim
#define NB 8      // batch
#define HH 64
#define WW 64

// Scratch: transformed codebook T[m][k][c]
__device__ float g_T[MG * KC * DD];
// Pre-split wq in smem-ready layout: [m][chunk(2)][hi/lo(2)] planes of 16KB.
__device__ __align__(1024) uint8_t g_Wsplit[MG * 2 * 2 * 16384];

// ---- L2 cache-policy helpers ----
__device__ __forceinline__ uint64_t make_evict_last_policy() {
    uint64_t pol;
    asm("createpolicy.fractional.L2::evict_last.b64 %0, 1.0;" : "=l"(pol));
    return pol;
}
__device__ __forceinline__ float4 ldg_nc_el(const float4* p, uint64_t pol) {
    float4 v;
    asm volatile("ld.global.nc.L2::cache_hint.v4.f32 {%0,%1,%2,%3}, [%4], %5;"
                 : "=f"(v.x), "=f"(v.y), "=f"(v.z), "=f"(v.w)
                 : "l"(p), "l"(pol));
    return v;
}
__device__ __forceinline__ void stg_el_v2(float* p, float vx, float vy, uint64_t pol) {
    asm volatile("st.global.L2::cache_hint.v2.f32 [%0], {%1,%2}, %3;"
                 :: "l"(p), "f"(vx), "f"(vy), "l"(pol) : "memory");
}
__device__ __forceinline__ void stg_cs(float* p, float v) {
    asm volatile("st.global.cs.f32 [%0], %1;" :: "l"(p), "f"(v) : "memory");
}

// ---- smem / tensor-core helpers ----
__device__ __forceinline__ uint32_t smem_u32(const void* p) {
    uint32_t a;
    asm("{ .reg .u64 t; cvta.to.shared.u64 t, %1; cvt.u32.u64 %0, t; }"
        : "=r"(a) : "l"(p));
    return a;
}
__device__ __forceinline__ uint32_t sw128(uint32_t off) {   // SW128 swizzle
    return off ^ ((off >> 3) & 0x70);
}
__device__ __forceinline__ void ldm_x4(uint32_t* r, uint32_t addr) {
    asm volatile("ldmatrix.sync.aligned.m8n8.x4.shared.b16 {%0,%1,%2,%3}, [%4];"
                 : "=r"(r[0]), "=r"(r[1]), "=r"(r[2]), "=r"(r[3]) : "r"(addr));
}
__device__ __forceinline__ void mma_bf16(float* d, const uint32_t* a, const uint32_t* b) {
    asm volatile("mma.sync.aligned.m16n8k16.row.col.f32.bf16.bf16.f32 "
                 "{%0,%1,%2,%3}, {%4,%5,%6,%7}, {%8,%9}, {%0,%1,%2,%3};"
                 : "+f"(d[0]), "+f"(d[1]), "+f"(d[2]), "+f"(d[3])
                 : "r"(a[0]), "r"(a[1]), "r"(a[2]), "r"(a[3]),
                   "r"(b[0]), "r"(b[1]));
}
__device__ __forceinline__ void split2(float x, float y, uint32_t& hi, uint32_t& lo) {
    __nv_bfloat16 hx = __float2bfloat16_rn(x);
    __nv_bfloat16 hy = __float2bfloat16_rn(y);
    float rx = x - __bfloat162float(hx);
    float ry = y - __bfloat162float(hy);
    __nv_bfloat16 lx = __float2bfloat16_rn(rx);
    __nv_bfloat16 ly = __float2bfloat16_rn(ry);
    hi = ((uint32_t)__bfloat16_as_ushort(hy) << 16) | __bfloat16_as_ushort(hx);
    lo = ((uint32_t)__bfloat16_as_ushort(ly) << 16) | __bfloat16_as_ushort(lx);
}

// ---------------------------------------------------------------------------
// Prep: split wq into bf16 hi/lo planes, swizzled like phase1's smem B.
// grid = (16 slices, 8 m) = 128 blocks, 1 float4 per thread.
// ---------------------------------------------------------------------------
__global__ void prep_wq(const float* __restrict__ wq) {
    const int slice = blockIdx.x;   // 0..15
    const int m     = blockIdx.y;   // 0..7
    const int tid   = threadIdx.x;
    const float* Wm = wq + (size_t)m * DD * DD;

    int e = (slice * 256 + tid) * 4;   // element index in [0, 16384)
    int c = e >> 7;                    // row 0..127
    int d = e & 127;
    int chunk = d >> 6;
    int dc = d & 63;
    float4 f = *reinterpret_cast<const float4*>(&Wm[c * DD + d]);
    uint32_t h01, l01, h23, l23;
    split2(f.x, f.y, h01, l01);
    split2(f.z, f.w, h23, l23);
    uint32_t off = sw128((uint32_t)(c * 128 + dc * 2));
    uint8_t* hiPlane = g_Wsplit + (((size_t)m * 2 + chunk) * 2 + 0) * 16384;
    uint8_t* loPlane = g_Wsplit + (((size_t)m * 2 + chunk) * 2 + 1) * 16384;
    *reinterpret_cast<uint2*>(hiPlane + off) = make_uint2(h01, h23);
    *reinterpret_cast<uint2*>(loPlane + off) = make_uint2(l01, l23);
}

// ---------------------------------------------------------------------------
// Phase 1 v2 (single wave): T[m][k][c] = codebook[m][k] @ wq[m]^T + bq
// grid = (32 k-tiles, 8 m) = 256 blocks; block = 256 (8 warps); tile
// 128k x 128c; warp tile 32k x 64c (warp_k = wid&3, warp_c = wid>>2).
// 96KB dynamic smem: A both chunks resident (Ah/Al 32KB), B single-chunk
// double-use (Bh/Bl 16KB). 2 blocks/SM x 148 = 296 >= 256 -> ONE wave.
// ---------------------------------------------------------------------------
__global__ void __launch_bounds__(256, 2) phase1_gemm(
    const float* __restrict__ codebook,
    const float* __restrict__ bq)
{
    extern __shared__ __align__(1024) uint8_t smem[];
    uint8_t* Ah = smem;              // 32KB: [chunk][128 rows][128B]
    uint8_t* Al = smem + 32768;      // 32KB
    uint8_t* Bh = smem + 65536;      // 16KB: [128 rows][128B]
    uint8_t* Bl = smem + 81920;      // 16KB
    const uint32_t Ah_s = smem_u32(Ah), Al_s = smem_u32(Al);
    const uint32_t Bh_s = smem_u32(Bh), Bl_s = smem_u32(Bl);

    const int m  = blockIdx.y;
    const int k0 = blockIdx.x * 128;
    const int tid  = threadIdx.x;
    const int lane = tid & 31;
    const int wid  = tid >> 5;      // 0..7
    const int warp_k = wid & 3;     // k strip of 32
    const int warp_c = wid >> 2;    // c strip of 64

    float acc[2][8][4];
    #pragma unroll
    for (int i = 0; i < 2; i++)
        #pragma unroll
        for (int j = 0; j < 8; j++)
            #pragma unroll
            for (int q = 0; q < 4; q++) acc[i][j][q] = 0.f;

    const float* Abase = codebook + ((size_t)m * KC + k0) * DD;
    const uint8_t* Wbase = g_Wsplit + (size_t)m * 4 * 16384;

    // --- prologue ---
    // B chunk0 copy: each plane 16KB = 1024 x 16B; 4 x 16B per thread
    #pragma unroll
    for (int j = 0; j < 4; j++) {
        uint32_t o = (uint32_t)(tid + j * 256) * 16;
        *reinterpret_cast<uint4*>(Bh + o) = *reinterpret_cast<const uint4*>(Wbase + o);
        *reinterpret_cast<uint4*>(Bl + o) = *reinterpret_cast<const uint4*>(Wbase + 16384 + o);
    }
    // A both chunks: 128 rows x 128 d fp32 -> bf16 hi/lo; 16 float4 per thread
    #pragma unroll
    for (int i = 0; i < 16; i++) {
        int e = (i * 256 + tid) * 4;        // 0..16383
        int row = e >> 7;                   // 0..127
        int d   = e & 127;
        int chunk = d >> 6;
        int dc    = d & 63;
        float4 f = *reinterpret_cast<const float4*>(&Abase[row * DD + d]);
        uint32_t h01, l01, h23, l23;
        split2(f.x, f.y, h01, l01);
        split2(f.z, f.w, h23, l23);
        uint32_t off = (uint32_t)chunk * 16384 + sw128((uint32_t)(row * 128 + dc * 2));
        *reinterpret_cast<uint2*>(Ah + off) = make_uint2(h01, h23);
        *reinterpret_cast<uint2*>(Al + off) = make_uint2(l01, l23);
    }
    __syncthreads();

    #pragma unroll
    for (int chunk = 0; chunk < 2; chunk++) {
        const uint32_t Ach = Ah_s + chunk * 16384;
        const uint32_t Alc = Al_s + chunk * 16384;
        #pragma unroll
        for (int ks = 0; ks < 4; ks++) {
            const int kcol = ks * 16;
            uint32_t ah[2][4], al[2][4];
            #pragma unroll
            for (int ma = 0; ma < 2; ma++) {
                int row = warp_k * 32 + ma * 16 + (lane & 7) + ((lane >> 3) & 1) * 8;
                int col = kcol + (lane >> 4) * 8;
                uint32_t off = sw128((uint32_t)(row * 128 + col * 2));
                ldm_x4(ah[ma], Ach + off);
                ldm_x4(al[ma], Alc + off);
            }
            uint32_t bh[8][2], bl[8][2];
            #pragma unroll
            for (int pr = 0; pr < 4; pr++) {
                int row = warp_c * 64 + pr * 16 + (lane & 7) + (lane >> 4) * 8;
                int col = kcol + ((lane >> 3) & 1) * 8;
                uint32_t off = sw128((uint32_t)(row * 128 + col * 2));
                uint32_t r[4];
                ldm_x4(r, Bh_s + off);
                bh[2 * pr][0] = r[0]; bh[2 * pr][1] = r[1];
                bh[2 * pr + 1][0] = r[2]; bh[2 * pr + 1][1] = r[3];
                ldm_x4(r, Bl_s + off);
                bl[2 * pr][0] = r[0]; bl[2 * pr][1] = r[1];
                bl[2 * pr + 1][0] = r[2]; bl[2 * pr + 1][1] = r[3];
            }
            #pragma unroll
            for (int ma = 0; ma < 2; ma++)
                #pragma unroll
                for (int na = 0; na < 8; na++) {
                    mma_bf16(acc[ma][na], ah[ma], bh[na]);
                    mma_bf16(acc[ma][na], ah[ma], bl[na]);
                    mma_bf16(acc[ma][na], al[ma], bh[na]);
                }
        }

        if (chunk == 0) {
            __syncthreads();   // chunk0 B reads done before overwrite
            #pragma unroll
            for (int j = 0; j < 4; j++) {
                uint32_t o = (uint32_t)(tid + j * 256) * 16;
                *reinterpret_cast<uint4*>(Bh + o) =
                    *reinterpret_cast<const uint4*>(Wbase + 32768 + o);
                *reinterpret_cast<uint4*>(Bl + o) =
                    *reinterpret_cast<const uint4*>(Wbase + 49152 + o);
            }
            __syncthreads();
        }
    }

    // Epilogue: bias + evict_last T stores
    uint64_t pol = make_evict_last_policy();
    float* Tm = g_T + ((size_t)m * KC + k0) * DD;
    #pragma unroll
    for (int ma = 0; ma < 2; ma++) {
        int r0 = warp_k * 32 + ma * 16 + (lane >> 2);
        #pragma unroll
        for (int na = 0; na < 8; na++) {
            int cg = warp_c * 64 + na * 8 + 2 * (lane & 3);
            float bx = bq[m * DD + cg], by = bq[m * DD + cg + 1];
            stg_el_v2(&Tm[(size_t)r0 * DD + cg],
                      acc[ma][na][0] + bx, acc[ma][na][1] + by, pol);
            stg_el_v2(&Tm[(size_t)(r0 + 8) * DD + cg],
                      acc[ma][na][2] + bx, acc[ma][na][3] + by, pol);
        }
    }
}

// ---------------------------------------------------------------------------
// Phase 2 (m-fused, software-pipelined; initial sync removed):
// each block handles 32 tokens for ALL 8 m-groups.
// grid = (h-halves=128, n=8) = 1024 blocks, block = 256, smem 34KB -> 6/SM.
// ---------------------------------------------------------------------------
__global__ void __launch_bounds__(256, 6) phase2_gather(
    const int* __restrict__ codes,
    float* __restrict__ out)
{
    const int h  = blockIdx.x >> 1;
    const int w0 = (blockIdx.x & 1) * 32;
    const int n  = blockIdx.y;
    const int tid  = threadIdx.x;
    const int lane = tid & 31;
    const int wid  = tid >> 5;   // 0..7

    __shared__ float s[2][32][132];
    __shared__ int scode[32][8];

    const size_t code_base = (((size_t)n * HH + h) * WW + w0) * MG;

    // Stage all codes (coalesced 1KB); consumed from m=1 onward.
    {
        int w = tid >> 3, mm = tid & 7;
        scode[w][mm] = codes[code_base + (size_t)w * MG + mm] & (KC - 1);
    }

    uint64_t pol = make_evict_last_policy();

    // m=0 gather issued immediately: each gather thread loads its own code
    // (8 lanes same addr -> broadcast). No initial __syncthreads needed; the
    // sync inside the loop orders scode for m>=1.
    float4 g[4];
    #pragma unroll
    for (int t = 0; t < 4; t++) {
        int w = wid * 4 + t;
        int c0 = codes[code_base + (size_t)w * MG] & (KC - 1);
        const float4* row = reinterpret_cast<const float4*>(g_T + (size_t)c0 * DD);
        g[t] = ldg_nc_el(row + lane, pol);
    }

    const int wl = tid & 31;
    const int cq = tid >> 5;   // 0..7

    #pragma unroll
    for (int mm = 0; mm < MG; mm++) {
        const int st = mm & 1;
        #pragma unroll
        for (int t = 0; t < 4; t++) {
            int w = wid * 4 + t;
            *reinterpret_cast<float4*>(&s[st][w][lane * 4]) = g[t];
        }
        __syncthreads();

        if (mm < MG - 1) {
            const float* Tn = g_T + (size_t)(mm + 1) * KC * DD;
            #pragma unroll
            for (int t = 0; t < 4; t++) {
                int w = wid * 4 + t;
                const float4* row = reinterpret_cast<const float4*>(
                    Tn + (size_t)scode[w][mm + 1] * DD);
                g[t] = ldg_nc_el(row + lane, pol);
            }
        }

        float* outbase = out +
            ((((size_t)n * (MG * DD) + mm * DD) * HH + h) * WW) + w0 + wl;
        #pragma unroll
        for (int pass = 0; pass < 4; pass++) {
            int c0 = cq * 4 + 32 * pass;
            float4 v = *reinterpret_cast<const float4*>(&s[st][wl][c0]);
            stg_cs(&outbase[(size_t)(c0 + 0) * HH * WW], v.x);
            stg_cs(&outbase[(size_t)(c0 + 1) * HH * WW], v.y);
            stg_cs(&outbase[(size_t)(c0 + 2) * HH * WW], v.z);
            stg_cs(&outbase[(size_t)(c0 + 3) * HH * WW], v.w);
        }
    }
}

// ---------------------------------------------------------------------------
// Launch. Inputs (metadata order): codes[int32], codebook[f32], wq[f32], bq[f32]
// ---------------------------------------------------------------------------
extern "C" void kernel_launch(void* const* d_in, const int* in_sizes, int n_in,
                              void* d_out, int out_size) {
    const int*   codes    = (const int*)d_in[0];
    const float* codebook = (const float*)d_in[1];
    const float* wq       = (const float*)d_in[2];
    const float* bq       = (const float*)d_in[3];
    float* out = (float*)d_out;

    const int P1_SMEM = 98304;   // 96KB dynamic smem
    cudaFuncSetAttribute(phase1_gemm,
                         cudaFuncAttributeMaxDynamicSharedMemorySize, P1_SMEM);

    dim3 gp(16, MG);
    prep_wq<<<gp, 256>>>(wq);

    dim3 g1(KC / 128, MG);
    phase1_gemm<<<g1, 256, P1_SMEM>>>(codebook, bq);

    dim3 g2(HH * 2, NB);
    phase2_gather<<<g2, 256>>>(codes, out);
}